// round 9
// baseline (speedup 1.0000x reference)
#include <cuda_runtime.h>
#include <cuda_fp16.h>
#include <stdint.h>
#include <math.h>

#define BB 2048
#define LL 10
#define VOCAB 1974
#define DD 512
#define HH 8
#define DI 2048
#define NLAY 6
#define BOARD 70
#define NTOK (BB*LL)       /* 20480 */
#define NBRD (BB*BOARD)    /* 143360 */
#define VPAD 2048

#if defined(__CUDA_ARCH_FEAT_SM103_ALL) || defined(__CUDA_ARCH_FEAT_SM100_ALL) || defined(__CUDA_ARCH_FEAT_SM101_ALL)
#define TC5 1
#else
#define TC5 0
#endif

// ---- weight arena: per-layer blocks, [N,K] (g_wt) and [K,N] (g_wf) ----
#define PL       4194304ull
#define R_SAQKV  0ull
#define R_CAQ    786432ull
#define R_CAKV   1048576ull
#define R_SAO    1572864ull
#define R_CAO    1835008ull
#define R_FF1    2097152ull
#define R_FF2    3145728ull
#define OFF_FC   25165824ull
#define WTOT     26214400ull

// ---------------- scratch (static device buffers) ----------------
__device__ float  g_x   [NTOK*DD];
__device__ float  g_fcb [VPAD];
__device__ float  g_bqkv[NLAY*1536];
__device__ __half g_xn  [NTOK*DD];
__device__ __half g_q   [NTOK*DD];
__device__ __half g_qkv [NTOK*1536];
__device__ __half g_ao  [NTOK*DD];
__device__ __half g_h   [NTOK*DI];
__device__ __half g_ckv [(size_t)NBRD*1024];
__device__ __half g_bf  [(size_t)NBRD*DD];
__device__ __half g_wf  [WTOT];    // [K,N]  (mma.sync fallback)
__device__ __half g_wt  [WTOT];    // [N,K]  (tcgen05)

// ---------------- prep: weights -> both fp16 layouts (one launch) ----------------
__global__ void wprep_k(const float* __restrict__ sawq, const float* __restrict__ sawkv,
                        const float* __restrict__ sawo, const float* __restrict__ cawq,
                        const float* __restrict__ cawkv, const float* __restrict__ cawo,
                        const float* __restrict__ ffw1, const float* __restrict__ ffw2,
                        const float* __restrict__ fcw) {
    size_t i = (size_t)blockIdx.x * blockDim.x + threadIdx.x;
    if (i >= WTOT) return;
    float v; __half h;
    if (i >= OFF_FC) {
        size_t r = i - OFF_FC;
        int n = (int)(r / 512), k = (int)(r % 512);
        v = (n < VOCAB) ? fcw[(size_t)k * VOCAB + n] : 0.f;
        h = __float2half_rn(v);
        g_wt[i] = h;
        g_wf[OFF_FC + (size_t)k * VPAD + n] = h;
        return;
    }
    size_t l = i / PL, r = i % PL;
    size_t regb; int n, k, N;
    if (r < R_CAQ) {
        regb = R_SAQKV; size_t r2 = r; N = 1536;
        n = (int)(r2 / 512); k = (int)(r2 % 512);
        v = (n < 512) ? sawq [l * 262144 + (size_t)k * 512  + n]
                      : sawkv[l * 524288 + (size_t)k * 1024 + (n - 512)];
    } else if (r < R_CAKV) {
        regb = R_CAQ; size_t r2 = r - R_CAQ; N = 512;
        n = (int)(r2 / 512); k = (int)(r2 % 512);
        v = cawq[l * 262144 + (size_t)k * 512 + n];
    } else if (r < R_SAO) {
        regb = R_CAKV; size_t r2 = r - R_CAKV; N = 1024;
        n = (int)(r2 / 512); k = (int)(r2 % 512);
        v = cawkv[l * 524288 + (size_t)k * 1024 + n];
    } else if (r < R_CAO) {
        regb = R_SAO; size_t r2 = r - R_SAO; N = 512;
        n = (int)(r2 / 512); k = (int)(r2 % 512);
        v = sawo[l * 262144 + (size_t)k * 512 + n];
    } else if (r < R_FF1) {
        regb = R_CAO; size_t r2 = r - R_CAO; N = 512;
        n = (int)(r2 / 512); k = (int)(r2 % 512);
        v = cawo[l * 262144 + (size_t)k * 512 + n];
    } else if (r < R_FF2) {
        regb = R_FF1; size_t r2 = r - R_FF1; N = 2048;
        n = (int)(r2 / 512); k = (int)(r2 % 512);
        v = ffw1[l * 1048576 + (size_t)k * 2048 + n];
    } else {
        regb = R_FF2; size_t r2 = r - R_FF2; N = 512;
        n = (int)(r2 / 2048); k = (int)(r2 % 2048);
        v = ffw2[l * 1048576 + (size_t)k * 512 + n];
    }
    h = __float2half_rn(v);
    g_wt[i] = h;
    g_wf[l * PL + regb + (size_t)k * N + n] = h;
}

__global__ void bconv_k(const float* __restrict__ boards) {
    size_t i = (size_t)blockIdx.x * blockDim.x + threadIdx.x;
    g_bf[i] = __float2half_rn(boards[i]);
}

// fcb copy + qkv-bias concat + embedding, one launch
__global__ void misc_k(const float* __restrict__ fcb,
                       const float* __restrict__ sa_bq, const float* __restrict__ sa_bkv,
                       const int* __restrict__ moves,
                       const float* __restrict__ emb, const float* __restrict__ pos) {
    size_t i = (size_t)blockIdx.x * blockDim.x + threadIdx.x;
    if (i < VPAD) g_fcb[i] = (i < VOCAB) ? fcb[i] : 0.f;
    if (i < NLAY * 1536) {
        int l = (int)(i / 1536), j = (int)(i % 1536);
        g_bqkv[i] = (j < 512) ? sa_bq[l * 512 + j] : sa_bkv[l * 1024 + (j - 512)];
    }
    if (i < (size_t)NTOK * DD) {
        int tok = (int)(i / DD), d = (int)(i % DD);
        g_x[i] = emb[(size_t)moves[tok] * DD + d] * 22.62741699796952f
               + pos[(size_t)(tok % LL) * DD + d];
    }
}

// ---------------- layernorm -> fp16 ----------------
__global__ __launch_bounds__(256) void ln_k(const float* __restrict__ X,
                                            const float* __restrict__ g,
                                            const float* __restrict__ b,
                                            __half* __restrict__ Y) {
    int row = blockIdx.x;
    const float2* x2 = (const float2*)(X + (size_t)row * DD);
    float2 v = x2[threadIdx.x];
    float s  = v.x + v.y;
    float ss = v.x * v.x + v.y * v.y;
    #pragma unroll
    for (int o = 16; o; o >>= 1) {
        s  += __shfl_down_sync(0xffffffffu, s,  o);
        ss += __shfl_down_sync(0xffffffffu, ss, o);
    }
    __shared__ float rs[8], rss[8];
    int w = threadIdx.x >> 5;
    if ((threadIdx.x & 31) == 0) { rs[w] = s; rss[w] = ss; }
    __syncthreads();
    if (threadIdx.x == 0) {
        float a = 0.f, c = 0.f;
        #pragma unroll
        for (int i = 0; i < 8; i++) { a += rs[i]; c += rss[i]; }
        rs[0] = a; rss[0] = c;
    }
    __syncthreads();
    float mean = rs[0] * (1.0f / DD);
    float var  = rss[0] * (1.0f / DD) - mean * mean;
    float rstd = rsqrtf(var + 1e-5f);
    float2 gg = ((const float2*)g)[threadIdx.x];
    float2 bb = ((const float2*)b)[threadIdx.x];
    size_t base = (size_t)row * DD + threadIdx.x * 2;
    Y[base]     = __float2half_rn((v.x - mean) * rstd * gg.x + bb.x);
    Y[base + 1] = __float2half_rn((v.y - mean) * rstd * gg.y + bb.y);
}

#if TC5
__device__ __forceinline__ uint32_t elect1() {
    uint32_t p;
    asm volatile("{\n\t.reg .pred p;\n\telect.sync _|p, 0xFFFFFFFF;\n\tselp.b32 %0, 1, 0, p;\n\t}"
                 : "=r"(p));
    return p;
}
#endif

#define MB_WAIT(mbar, ph) do {                                                        \
    uint32_t _d;                                                                      \
    do {                                                                              \
        asm volatile("{\n\t.reg .pred p;\n\t"                                         \
            "mbarrier.try_wait.parity.acquire.cta.shared::cta.b64 p, [%1], %2, 0x989680;\n\t" \
            "selp.b32 %0, 1, 0, p;\n\t}"                                              \
            : "=r"(_d) : "r"(mbar), "r"((uint32_t)(ph)) : "memory");                  \
    } while (!_d);                                                                    \
} while (0)

// SW128 K-major descriptor base: layout=SW128(2), version=1, SBO=64, LBO=1
#define DESC_BASE ((2ull<<61)|(1ull<<46)|(64ull<<32)|(1ull<<16))
// idesc kind::f16: dtype=F32, atype=btype=F16(0), N=256, M=128
#define IDESC_F16 ((1u<<4) | (32u<<17) | (8u<<24))

#define STAGE_SZ 49152                       /* A 16KB + B 32KB */
#define OSM_OFF  (1024 + 3*STAGE_SZ)         /* 148480 */
#define TG_SMEM  (OSM_OFF + 33792)           /* 182272 */

// ---------------- persistent warp-specialized GEMM: C[M,Nc] = A[M,K] @ W ----------------
// epi: 0 +bias->f32  1 relu(+bias)->f16  2 +bias+res->f32  3 +bias->f16
__global__ __launch_bounds__(256) void tgemm_k(
    const __half* __restrict__ A, const __half* __restrict__ W,
    const __half* __restrict__ Wt,
    const float* __restrict__ bias, const float* __restrict__ res,
    float* __restrict__ Cf, __half* __restrict__ Ch,
    int M, int N, int K, int Nc, int epi)
{
    extern __shared__ __align__(16) char smem[];
    const int tid  = threadIdx.x;
    const int warp = tid >> 5;
    const int nbN = N >> 8;
    const int ntiles = (M >> 7) * nbN;
    int nt = 0;
    for (int t = blockIdx.x; t < ntiles; t += gridDim.x) nt++;
    if (nt == 0) return;

#if TC5
    const uint32_t sb = (uint32_t)__cvta_generic_to_shared(smem);
    const uint32_t MB_L0 = sb + 16, MB_MMA0 = sb + 32, MB_FREE0 = sb + 48;
    const uint32_t SMT = sb + 1024;
    const int KT = K >> 6;
    const int G = nt * KT;

    if (warp == 0) {
        asm volatile("tcgen05.alloc.cta_group::1.sync.aligned.shared::cta.b32 [%0], 512;"
                     :: "r"(sb) : "memory");
        asm volatile("tcgen05.relinquish_alloc_permit.cta_group::1.sync.aligned;");
    }
    if (tid == 0) {
        #pragma unroll
        for (int q = 0; q < 6; q++)
            asm volatile("mbarrier.init.shared.b64 [%0], 1;" :: "r"(sb + 16 + q * 8) : "memory");
    }
    __syncthreads();
    uint32_t tmem;
    asm volatile("ld.shared.b32 %0, [%1];" : "=r"(tmem) : "r"(sb));

    if (tid < 128) {
        // ================= WG0: loader + MMA issuer =================
        uint32_t swo[8], go[8];
        #pragma unroll
        for (int i = 0; i < 8; i++) {
            int c = tid + i * 128;
            int row = c >> 3, cb = (c & 7) << 4;
            int bo = (row << 7) + cb;
            swo[i] = (uint32_t)(bo ^ ((bo >> 3) & 0x70));
            go[i]  = (uint32_t)(row * K + (cb >> 1));
        }
        const uint32_t goB2 = (uint32_t)(K << 7);   // +128 rows

        // load cursor
        int tc_l = blockIdx.x, kt_l = 0, s_l = 0;
        const __half *gA_l, *gB_l;
        {
            int mb = tc_l / nbN, nb = tc_l - mb * nbN;
            gA_l = A  + (size_t)mb * 128 * K;
            gB_l = Wt + (size_t)nb * 256 * K;
        }

        #define LOADT() do {                                                          \
            const __half* aP = gA_l + kt_l * 64;                                      \
            const __half* bP = gB_l + kt_l * 64;                                      \
            uint32_t baA = SMT + s_l * STAGE_SZ, baB = baA + 16384;                   \
            _Pragma("unroll")                                                         \
            for (int i = 0; i < 8; i++) {                                             \
                asm volatile("cp.async.cg.shared.global [%0], [%1], 16;"              \
                    :: "r"(baA + swo[i]), "l"((const void*)(aP + go[i])) : "memory"); \
                asm volatile("cp.async.cg.shared.global [%0], [%1], 16;"              \
                    :: "r"(baB + swo[i]), "l"((const void*)(bP + go[i])) : "memory"); \
                asm volatile("cp.async.cg.shared.global [%0], [%1], 16;"              \
                    :: "r"(baB + 16384 + swo[i]), "l"((const void*)(bP + goB2 + go[i])) : "memory"); \
            }                                                                         \
        } while (0)

        #define ADV_L() do {                                                          \
            if (++s_l == 3) s_l = 0;                                                  \
            if (++kt_l == KT) {                                                       \
                kt_l = 0; tc_l += gridDim.x;                                          \
                if (tc_l < ntiles) {                                                  \
                    int mb = tc_l / nbN, nb = tc_l - mb * nbN;                        \
                    gA_l = A  + (size_t)mb * 128 * K;                                 \
                    gB_l = Wt + (size_t)nb * 256 * K;                                 \
                }                                                                     \
            }                                                                         \
        } while (0)

        // prologue: 2 stages ahead
        LOADT(); asm volatile("cp.async.commit_group;" ::: "memory"); ADV_L();
        if (G > 1) LOADT();
        asm volatile("cp.async.commit_group;" ::: "memory");
        if (G > 1) ADV_L();
        int g_load = 2;

        int i_m = 0, kt_m = 0, s_m = 0;
        for (int g = 0; g < G; g++) {
            if (g_load < G) {
                int j = g_load - 3;
                if (j >= 0) MB_WAIT(MB_L0 + (uint32_t)(j & 1) * 8, (uint32_t)((j >> 1) & 1));
                LOADT();
                ADV_L();
            }
            g_load++;
            asm volatile("cp.async.commit_group;" ::: "memory");
            asm volatile("cp.async.wait_group 2;" ::: "memory");
            asm volatile("fence.proxy.async.shared::cta;" ::: "memory");
            asm volatile("bar.sync 1, 128;" ::: "memory");
            if (warp == 0 && elect1()) {
                uint32_t r = (uint32_t)(i_m & 1);
                if (kt_m == 0 && i_m >= 2) {
                    int u = i_m >> 1;
                    MB_WAIT(MB_FREE0 + r * 8, (uint32_t)((u - 1) & 1));
                }
                uint32_t dt = tmem + r * 256;
                uint32_t base = SMT + s_m * STAGE_SZ;
                uint64_t ad = DESC_BASE | (uint64_t)((base >> 4) & 0x3FFF);
                uint64_t bd = DESC_BASE | (uint64_t)(((base + 16384) >> 4) & 0x3FFF);
                #pragma unroll
                for (int s = 0; s < 4; s++) {
                    uint32_t en = (kt_m > 0 || s > 0) ? 1u : 0u;
                    asm volatile(
                        "{\n\t.reg .pred p;\n\tsetp.ne.u32 p, %5, 0;\n\t"
                        "tcgen05.mma.cta_group::1.kind::f16 [%0], %1, %2, %3, {%4,%4,%4,%4}, p;\n\t}"
                        :: "r"(dt), "l"(ad + s * 2), "l"(bd + s * 2),
                           "r"(IDESC_F16), "r"(0u), "r"(en) : "memory");
                }
                asm volatile(
                    "tcgen05.commit.cta_group::1.mbarrier::arrive::one.shared::cluster.b64 [%0];"
                    :: "r"(MB_L0 + (uint32_t)(g & 1) * 8) : "memory");
                if (kt_m == KT - 1)
                    asm volatile(
                        "tcgen05.commit.cta_group::1.mbarrier::arrive::one.shared::cluster.b64 [%0];"
                        :: "r"(MB_MMA0 + r * 8) : "memory");
            }
            if (++s_m == 3) s_m = 0;
            if (++kt_m == KT) { kt_m = 0; i_m++; }
        }
        #undef LOADT
        #undef ADV_L
    } else {
        // ================= WG1: epilogue =================
        int wg   = tid - 128;            // 0..127 (row)
        int w2   = wg >> 5;              // 0..3
        int l2   = wg & 31;
        float* osm = (float*)(smem + OSM_OFF);   // [128][66]
        for (int i = 0; i < nt; i++) {
            int t = blockIdx.x + i * (int)gridDim.x;
            int mb = t / nbN, nb = t - mb * nbN;
            int m0 = mb << 7, n0 = nb << 8;
            uint32_t r = (uint32_t)(i & 1);
            MB_WAIT(MB_MMA0 + r * 8, (uint32_t)((i >> 1) & 1));
            asm volatile("tcgen05.fence::after_thread_sync;" ::: "memory");
            for (int cb = 0; cb < 256; cb += 64) {
                uint32_t d0[32], d1[32];
                asm volatile(
                    "tcgen05.ld.sync.aligned.32x32b.x32.b32 "
                    "{%0,%1,%2,%3,%4,%5,%6,%7,%8,%9,%10,%11,%12,%13,%14,%15,"
                    "%16,%17,%18,%19,%20,%21,%22,%23,%24,%25,%26,%27,%28,%29,%30,%31}, [%32];"
                    : "=r"(d0[0]),"=r"(d0[1]),"=r"(d0[2]),"=r"(d0[3]),"=r"(d0[4]),"=r"(d0[5]),
                      "=r"(d0[6]),"=r"(d0[7]),"=r"(d0[8]),"=r"(d0[9]),"=r"(d0[10]),"=r"(d0[11]),
                      "=r"(d0[12]),"=r"(d0[13]),"=r"(d0[14]),"=r"(d0[15]),"=r"(d0[16]),"=r"(d0[17]),
                      "=r"(d0[18]),"=r"(d0[19]),"=r"(d0[20]),"=r"(d0[21]),"=r"(d0[22]),"=r"(d0[23]),
                      "=r"(d0[24]),"=r"(d0[25]),"=r"(d0[26]),"=r"(d0[27]),"=r"(d0[28]),"=r"(d0[29]),
                      "=r"(d0[30]),"=r"(d0[31])
                    : "r"(tmem + r * 256 + cb));
                asm volatile(
                    "tcgen05.ld.sync.aligned.32x32b.x32.b32 "
                    "{%0,%1,%2,%3,%4,%5,%6,%7,%8,%9,%10,%11,%12,%13,%14,%15,"
                    "%16,%17,%18,%19,%20,%21,%22,%23,%24,%25,%26,%27,%28,%29,%30,%31}, [%32];"
                    : "=r"(d1[0]),"=r"(d1[1]),"=r"(d1[2]),"=r"(d1[3]),"=r"(d1[4]),"=r"(d1[5]),
                      "=r"(d1[6]),"=r"(d1[7]),"=r"(d1[8]),"=r"(d1[9]),"=r"(d1[10]),"=r"(d1[11]),
                      "=r"(d1[12]),"=r"(d1[13]),"=r"(d1[14]),"=r"(d1[15]),"=r"(d1[16]),"=r"(d1[17]),
                      "=r"(d1[18]),"=r"(d1[19]),"=r"(d1[20]),"=r"(d1[21]),"=r"(d1[22]),"=r"(d1[23]),
                      "=r"(d1[24]),"=r"(d1[25]),"=r"(d1[26]),"=r"(d1[27]),"=r"(d1[28]),"=r"(d1[29]),
                      "=r"(d1[30]),"=r"(d1[31])
                    : "r"(tmem + r * 256 + cb + 32));
                asm volatile("tcgen05.wait::ld.sync.aligned;" ::: "memory");
                float* rowp = osm + wg * 66;
                #pragma unroll
                for (int c = 0; c < 32; c++) { rowp[c] = __uint_as_float(d0[c]); rowp[32 + c] = __uint_as_float(d1[c]); }
                asm volatile("bar.sync 2, 128;" ::: "memory");
                const int colb = n0 + cb;
                const int c2 = l2 * 2;
                if (colb + 64 <= Nc) {
                    float b0 = bias[colb + c2], b1 = bias[colb + c2 + 1];
                    for (int rr = w2; rr < 128; rr += 4) {
                        float v0 = osm[rr * 66 + c2] + b0;
                        float v1 = osm[rr * 66 + c2 + 1] + b1;
                        size_t off = (size_t)(m0 + rr) * Nc + colb + c2;
                        if (epi == 2) {
                            float2 rv = *(const float2*)(res + off);
                            *(float2*)(Cf + off) = make_float2(v0 + rv.x, v1 + rv.y);
                        } else if (epi == 0) {
                            *(float2*)(Cf + off) = make_float2(v0, v1);
                        } else {
                            if (epi == 1) { v0 = fmaxf(v0, 0.f); v1 = fmaxf(v1, 0.f); }
                            *(__half2*)(Ch + off) = __floats2half2_rn(v0, v1);
                        }
                    }
                } else {
                    for (int rr = w2; rr < 128; rr += 4) {
                        #pragma unroll
                        for (int q = 0; q < 2; q++) {
                            int c = colb + c2 + q;
                            if (c < Nc) {
                                float v = osm[rr * 66 + c2 + q] + bias[c];
                                size_t off = (size_t)(m0 + rr) * Nc + c;
                                if (epi == 2)      Cf[off] = v + res[off];
                                else if (epi == 0) Cf[off] = v;
                                else if (epi == 1) Ch[off] = __float2half_rn(fmaxf(v, 0.f));
                                else               Ch[off] = __float2half_rn(v);
                            }
                        }
                    }
                }
                asm volatile("bar.sync 2, 128;" ::: "memory");
            }
            asm volatile("tcgen05.fence::before_thread_sync;" ::: "memory");
            asm volatile("bar.sync 2, 128;" ::: "memory");
            if (tid == 128)
                asm volatile("mbarrier.arrive.shared.b64 _, [%0];" :: "r"(MB_FREE0 + r * 8) : "memory");
        }
    }

    __syncthreads();
    if (tid == 0) {
        #pragma unroll
        for (int q = 0; q < 6; q++)
            asm volatile("mbarrier.inval.shared.b64 [%0];" :: "r"(sb + 16 + q * 8) : "memory");
    }
    __syncthreads();
    if (warp == 0)
        asm volatile("tcgen05.dealloc.cta_group::1.sync.aligned.b32 %0, 512;" :: "r"(tmem));

#else
    // ================= mma.sync fallback (persistent, two 128-wide halves) =================
    const int lane = tid & 31;
    __half* AsB = (__half*)smem;              // [2][128][40]
    __half* WsB = (__half*)(smem + 20480);    // [2][32][136]
    #define ASO(s,r,c) (((s)*128+(r))*40+(c))
    #define WSO(s,r,c) (((s)*32+(r))*136+(c))
    const int wm = (warp & 1) * 64;
    const int wn = (warp >> 1) * 32;
    const int arow = tid >> 1, acol = (tid & 1) * 16;
    const int wrow = tid >> 3, wcol = (tid & 7) * 16;
    const int KT2 = K >> 5;

    for (int t = blockIdx.x; t < ntiles; t += gridDim.x) {
        int mb = t / nbN, nb = t - mb * nbN;
        for (int nh = 0; nh < 2; nh++) {
            int m0 = mb * 128, n0 = nb * 256 + nh * 128;
            __syncthreads();
            const __half* Abase = A + (size_t)(m0 + arow) * K + acol;
            const __half* Wbase = W + (size_t)wrow * N + n0 + wcol;
            float acc[4][4][4];
            #pragma unroll
            for (int i = 0; i < 4; i++)
                #pragma unroll
                for (int j = 0; j < 4; j++)
                    #pragma unroll
                    for (int q = 0; q < 4; q++) acc[i][j][q] = 0.f;

            #define LOAD_STAGE(s, kt) do {                                               \
                unsigned da = (unsigned)__cvta_generic_to_shared(&AsB[ASO(s, arow, acol)]); \
                const __half* sa = Abase + (kt) * 32;                                    \
                asm volatile("cp.async.cg.shared.global [%0], [%1], 16;\n"               \
                             "cp.async.cg.shared.global [%2], [%3], 16;"                 \
                             :: "r"(da), "l"(sa), "r"(da + 16), "l"(sa + 8));            \
                unsigned dw = (unsigned)__cvta_generic_to_shared(&WsB[WSO(s, wrow, wcol)]); \
                const __half* sw = Wbase + (size_t)((kt) * 32) * N;                      \
                asm volatile("cp.async.cg.shared.global [%0], [%1], 16;\n"               \
                             "cp.async.cg.shared.global [%2], [%3], 16;"                 \
                             :: "r"(dw), "l"(sw), "r"(dw + 16), "l"(sw + 8));            \
            } while (0)

            LOAD_STAGE(0, 0);
            asm volatile("cp.async.commit_group;");
            int buf = 0;
            for (int kt = 0; kt < KT2; kt++) {
                if (kt + 1 < KT2) LOAD_STAGE(buf ^ 1, kt + 1);
                asm volatile("cp.async.commit_group;");
                asm volatile("cp.async.wait_group 1;");
                __syncthreads();
                #pragma unroll
                for (int ks = 0; ks < 2; ks++) {
                    unsigned aF[4][4], bF[4][2];
                    #pragma unroll
                    for (int mt = 0; mt < 4; mt++) {
                        unsigned addr = (unsigned)__cvta_generic_to_shared(
                            &AsB[ASO(buf, wm + mt * 16 + (lane & 15), ks * 16 + (lane >> 4) * 8)]);
                        asm volatile("ldmatrix.sync.aligned.m8n8.x4.shared.b16 {%0,%1,%2,%3}, [%4];"
                            : "=r"(aF[mt][0]), "=r"(aF[mt][1]), "=r"(aF[mt][2]), "=r"(aF[mt][3])
                            : "r"(addr));
                    }
                    #pragma unroll
                    for (int nt2 = 0; nt2 < 4; nt2++) {
                        unsigned addr = (unsigned)__cvta_generic_to_shared(
                            &WsB[WSO(buf, ks * 16 + (lane & 15), wn + nt2 * 8)]);
                        asm volatile("ldmatrix.sync.aligned.m8n8.x2.trans.shared.b16 {%0,%1}, [%2];"
                            : "=r"(bF[nt2][0]), "=r"(bF[nt2][1]) : "r"(addr));
                    }
                    #pragma unroll
                    for (int mt = 0; mt < 4; mt++)
                        #pragma unroll
                        for (int nt2 = 0; nt2 < 4; nt2++) {
                            asm volatile(
                                "mma.sync.aligned.m16n8k16.row.col.f32.f16.f16.f32 "
                                "{%0,%1,%2,%3}, {%4,%5,%6,%7}, {%8,%9}, {%0,%1,%2,%3};"
                                : "+f"(acc[mt][nt2][0]), "+f"(acc[mt][nt2][1]),
                                  "+f"(acc[mt][nt2][2]), "+f"(acc[mt][nt2][3])
                                : "r"(aF[mt][0]), "r"(aF[mt][1]), "r"(aF[mt][2]), "r"(aF[mt][3]),
                                  "r"(bF[nt2][0]), "r"(bF[nt2][1]));
                        }
                }
                buf ^= 1;
                __syncthreads();
            }
            #pragma unroll
            for (int mt = 0; mt < 4; mt++) {
                int r0 = m0 + wm + mt * 16 + (lane >> 2);
                #pragma unroll
                for (int nt2 = 0; nt2 < 4; nt2++) {
                    int c0 = n0 + wn + nt2 * 8 + (lane & 3) * 2;
                    #pragma unroll
                    for (int q = 0; q < 4; q++) {
                        int rr = r0 + (q >> 1) * 8;
                        int c = c0 + (q & 1);
                        if (c < Nc) {
                            float v = acc[mt][nt2][q] + bias[c];
                            size_t off = (size_t)rr * Nc + c;
                            if (epi == 0)      Cf[off] = v;
                            else if (epi == 1) Ch[off] = __float2half_rn(fmaxf(v, 0.f));
                            else if (epi == 2) Cf[off] = v + res[off];
                            else               Ch[off] = __float2half_rn(v);
                        }
                    }
                }
            }
            #undef LOAD_STAGE
        }
    }
    #undef ASO
    #undef WSO
#endif
}

// ---------------- self attention: per (b,h), QKV packed rows of 1536 ----------------
__global__ __launch_bounds__(128) void selfattn_k(const __half* __restrict__ QKV,
                                                  const int* __restrict__ lengths,
                                                  __half* __restrict__ O) {
    int b = blockIdx.x, h = blockIdx.y;
    __shared__ float q[LL][65], k[LL][65], v[LL][65], s[LL][11];
    int tid = threadIdx.x;
    int len = lengths[b];
    for (int idx = tid; idx < LL * 64; idx += 128) {
        int i = idx >> 6, d = idx & 63;
        size_t base = ((size_t)(b * LL + i)) * 1536 + h * 64 + d;
        q[i][d] = __half2float(QKV[base]);
        k[i][d] = __half2float(QKV[base + 512]);
        v[i][d] = __half2float(QKV[base + 1024]);
    }
    __syncthreads();
    for (int idx = tid; idx < LL * LL; idx += 128) {
        int i = idx / LL, j = idx % LL;
        float acc = 0.f;
        #pragma unroll
        for (int d = 0; d < 64; d++) acc += q[i][d] * k[j][d];
        acc *= 0.125f;
        if (j > i || j >= len) acc = -1e30f;
        s[i][j] = acc;
    }
    __syncthreads();
    if (tid < LL) {
        float mx = -1e30f;
        #pragma unroll
        for (int j = 0; j < LL; j++) mx = fmaxf(mx, s[tid][j]);
        float sum = 0.f;
        #pragma unroll
        for (int j = 0; j < LL; j++) { float e = expf(s[tid][j] - mx); s[tid][j] = e; sum += e; }
        float inv = 1.0f / sum;
        #pragma unroll
        for (int j = 0; j < LL; j++) s[tid][j] *= inv;
    }
    __syncthreads();
    for (int idx = tid; idx < LL * 64; idx += 128) {
        int i = idx >> 6, d = idx & 63;
        float acc = 0.f;
        #pragma unroll
        for (int j = 0; j < LL; j++) acc += s[i][j] * v[j][d];
        O[((size_t)(b * LL + i)) * DD + h * 64 + d] = __float2half_rn(acc);
    }
}

// ---------------- cross attention: per (b,h), Lq=10, Lk=70 ----------------
__global__ __launch_bounds__(256) void crossattn_k(const __half* __restrict__ Q,
                                                   const __half* __restrict__ CKV,
                                                   __half* __restrict__ O) {
    int b = blockIdx.x, h = blockIdx.y;
    __shared__ float q[LL][65], kk[BOARD][65], vv[BOARD][65], s[LL][71];
    int tid = threadIdx.x;
    for (int idx = tid; idx < LL * 64; idx += 256) {
        int i = idx >> 6, d = idx & 63;
        q[i][d] = __half2float(Q[((size_t)(b * LL + i)) * DD + h * 64 + d]);
    }
    for (int idx = tid; idx < BOARD * 64; idx += 256) {
        int j = idx >> 6, d = idx & 63;
        size_t off = ((size_t)(b * BOARD + j)) * 1024 + h * 64 + d;
        kk[j][d] = __half2float(CKV[off]);
        vv[j][d] = __half2float(CKV[off + 512]);
    }
    __syncthreads();
    for (int idx = tid; idx < LL * BOARD; idx += 256) {
        int i = idx / BOARD, j = idx % BOARD;
        float acc = 0.f;
        #pragma unroll
        for (int d = 0; d < 64; d++) acc += q[i][d] * kk[j][d];
        s[i][j] = acc * 0.125f;
    }
    __syncthreads();
    if (tid < LL) {
        float mx = -1e30f;
        for (int j = 0; j < BOARD; j++) mx = fmaxf(mx, s[tid][j]);
        float sum = 0.f;
        for (int j = 0; j < BOARD; j++) { float e = expf(s[tid][j] - mx); s[tid][j] = e; sum += e; }
        float inv = 1.0f / sum;
        for (int j = 0; j < BOARD; j++) s[tid][j] *= inv;
    }
    __syncthreads();
    for (int idx = tid; idx < LL * 64; idx += 256) {
        int i = idx >> 6, d = idx & 63;
        float acc = 0.f;
        #pragma unroll
        for (int j = 0; j < BOARD; j++) acc += s[i][j] * vv[j][d];
        O[((size_t)(b * LL + i)) * DD + h * 64 + d] = __float2half_rn(acc);
    }
}

// ---------------- host ----------------
static __half *s_wf, *s_wt;

static void tgemm(const __half* A, size_t woff, const float* bias, const float* res,
                  float* Cf, __half* Ch, int M, int N, int K, int Nc, int epi) {
    int ntiles = (M / 128) * (N / 256);
    int grid = ntiles < 148 ? ntiles : 148;
    tgemm_k<<<grid, 256, TG_SMEM>>>(A, s_wf + woff, s_wt + woff, bias, res, Cf, Ch,
                                    M, N, K, Nc, epi);
}

extern "C" void kernel_launch(void* const* d_in, const int* in_sizes, int n_in,
                              void* d_out, int out_size) {
    const int*   moves   = (const int*)d_in[0];
    const int*   lengths = (const int*)d_in[1];
    const float* boards  = (const float*)d_in[2];
    const float* emb     = (const float*)d_in[3];
    const float* pos     = (const float*)d_in[4];
    const float* sa_ln_g = (const float*)d_in[5];
    const float* sa_ln_b = (const float*)d_in[6];
    const float* sa_wq   = (const float*)d_in[7];
    const float* sa_bq   = (const float*)d_in[8];
    const float* sa_wkv  = (const float*)d_in[9];
    const float* sa_bkv  = (const float*)d_in[10];
    const float* sa_wo   = (const float*)d_in[11];
    const float* sa_bo   = (const float*)d_in[12];
    const float* ca_ln_g = (const float*)d_in[13];
    const float* ca_ln_b = (const float*)d_in[14];
    const float* ca_wq   = (const float*)d_in[15];
    const float* ca_bq   = (const float*)d_in[16];
    const float* ca_wkv  = (const float*)d_in[17];
    const float* ca_bkv  = (const float*)d_in[18];
    const float* ca_wo   = (const float*)d_in[19];
    const float* ca_bo   = (const float*)d_in[20];
    const float* ff_ln_g = (const float*)d_in[21];
    const float* ff_ln_b = (const float*)d_in[22];
    const float* ff_w1   = (const float*)d_in[23];
    const float* ff_b1   = (const float*)d_in[24];
    const float* ff_w2   = (const float*)d_in[25];
    const float* ff_b2   = (const float*)d_in[26];
    const float* fin_g   = (const float*)d_in[27];
    const float* fin_b   = (const float*)d_in[28];
    const float* fc_w    = (const float*)d_in[29];
    const float* fc_b    = (const float*)d_in[30];
    float* out = (float*)d_out;

    cudaFuncSetAttribute(tgemm_k, cudaFuncAttributeMaxDynamicSharedMemorySize, TG_SMEM);

    float *px, *pfcb, *pbqkv;
    __half *pxn, *pq, *pqkv, *pao, *ph, *pckv, *pbf;
    cudaGetSymbolAddress((void**)&px,    g_x);
    cudaGetSymbolAddress((void**)&pfcb,  g_fcb);
    cudaGetSymbolAddress((void**)&pbqkv, g_bqkv);
    cudaGetSymbolAddress((void**)&pxn,   g_xn);
    cudaGetSymbolAddress((void**)&pq,    g_q);
    cudaGetSymbolAddress((void**)&pqkv,  g_qkv);
    cudaGetSymbolAddress((void**)&pao,   g_ao);
    cudaGetSymbolAddress((void**)&ph,    g_h);
    cudaGetSymbolAddress((void**)&pckv,  g_ckv);
    cudaGetSymbolAddress((void**)&pbf,   g_bf);
    cudaGetSymbolAddress((void**)&s_wf,  g_wf);
    cudaGetSymbolAddress((void**)&s_wt,  g_wt);

    // prep: 3 launches; launch #4 = layer-0 caKV (the ncu target)
    wprep_k<<<(unsigned)((WTOT + 511) / 512), 512>>>(sa_wq, sa_wkv, sa_wo, ca_wq, ca_wkv,
                                                     ca_wo, ff_w1, ff_w2, fc_w);
    bconv_k<<<(unsigned)(((size_t)NBRD * DD) / 512), 512>>>(boards);
    misc_k<<<(NTOK * DD) / 512, 512>>>(fc_b, sa_bq, sa_bkv, moves, emb, pos);

    // layer-0 cross-KV (depends only on boards) hoisted
    tgemm(pbf, R_CAKV, ca_bkv, nullptr, nullptr, pckv, NBRD, 1024, 512, 1024, 3);

    for (int i = 0; i < NLAY; i++) {
        size_t WB = (size_t)i * PL;

        // ---- self attention ----
        ln_k<<<NTOK, 256>>>(px, sa_ln_g + i * DD, sa_ln_b + i * DD, pxn);
        tgemm(pxn, WB + R_SAQKV, pbqkv + i * 1536, nullptr, nullptr, pqkv,
              NTOK, 1536, 512, 1536, 3);
        selfattn_k<<<dim3(BB, HH), 128>>>(pqkv, lengths, pao);
        tgemm(pao, WB + R_SAO, sa_bo + i * DD, px, px, nullptr,
              NTOK, 512, 512, 512, 2);

        // ---- cross attention ----
        ln_k<<<NTOK, 256>>>(px, ca_ln_g + i * DD, ca_ln_b + i * DD, pxn);
        tgemm(pxn, WB + R_CAQ, ca_bq + i * 512, nullptr, nullptr, pq,
              NTOK, 512, 512, 512, 3);
        if (i > 0)
            tgemm(pbf, WB + R_CAKV, ca_bkv + i * 1024, nullptr, nullptr, pckv,
                  NBRD, 1024, 512, 1024, 3);
        crossattn_k<<<dim3(BB, HH), 256>>>(pq, pckv, pao);
        tgemm(pao, WB + R_CAO, ca_bo + i * DD, px, px, nullptr,
              NTOK, 512, 512, 512, 2);

        // ---- FFN ----
        ln_k<<<NTOK, 256>>>(px, ff_ln_g + i * DD, ff_ln_b + i * DD, pxn);
        tgemm(pxn, WB + R_FF1, ff_b1 + i * DI, nullptr, nullptr, ph,
              NTOK, DI, 512, DI, 1);
        tgemm(ph, WB + R_FF2, ff_b2 + i * DD, px, px, nullptr,
              NTOK, 512, DI, 512, 2);
    }

    ln_k<<<NTOK, 256>>>(px, fin_g, fin_b, pxn);
    tgemm(pxn, OFF_FC, pfcb, nullptr, out, nullptr, NTOK, VPAD, 512, VOCAB, 0);
}

// round 10
// speedup vs baseline: 1.4462x; 1.4462x over previous
#include <cuda_runtime.h>
#include <cuda_fp16.h>
#include <stdint.h>
#include <math.h>

#define BB 2048
#define LL 10
#define VOCAB 1974
#define DD 512
#define HH 8
#define DI 2048
#define NLAY 6
#define BOARD 70
#define NTOK (BB*LL)       /* 20480 */
#define NBRD (BB*BOARD)    /* 143360 */
#define VPAD 2048

#if defined(__CUDA_ARCH_FEAT_SM103_ALL) || defined(__CUDA_ARCH_FEAT_SM100_ALL) || defined(__CUDA_ARCH_FEAT_SM101_ALL)
#define TC5 1
#else
#define TC5 0
#endif

// ---- weight arena: per-layer blocks, [N,K] (g_wt) and [K,N] (g_wf) ----
#define PL       4194304ull
#define R_SAQKV  0ull
#define R_CAQ    786432ull
#define R_CAKV   1048576ull
#define R_SAO    1572864ull
#define R_CAO    1835008ull
#define R_FF1    2097152ull
#define R_FF2    3145728ull
#define OFF_FC   25165824ull
#define WTOT     26214400ull

// ---------------- scratch (static device buffers) ----------------
__device__ float  g_x   [NTOK*DD];
__device__ float  g_fcb [VPAD];
__device__ float  g_bqkv[NLAY*1536];
__device__ __half g_xn  [NTOK*DD];
__device__ __half g_q   [NTOK*DD];
__device__ __half g_qkv [NTOK*1536];
__device__ __half g_ao  [NTOK*DD];
__device__ __half g_h   [NTOK*DI];
__device__ __half g_ckv [(size_t)NBRD*1024];
__device__ __half g_bf  [(size_t)NBRD*DD];
__device__ __half g_wf  [WTOT];    // [K,N]  (mma.sync fallback)
__device__ __half g_wt  [WTOT];    // [N,K]  (tcgen05)

// ---------------- prep: weights -> both fp16 layouts (one launch) ----------------
__global__ void wprep_k(const float* __restrict__ sawq, const float* __restrict__ sawkv,
                        const float* __restrict__ sawo, const float* __restrict__ cawq,
                        const float* __restrict__ cawkv, const float* __restrict__ cawo,
                        const float* __restrict__ ffw1, const float* __restrict__ ffw2,
                        const float* __restrict__ fcw) {
    size_t i = (size_t)blockIdx.x * blockDim.x + threadIdx.x;
    if (i >= WTOT) return;
    float v; __half h;
    if (i >= OFF_FC) {
        size_t r = i - OFF_FC;
        int n = (int)(r / 512), k = (int)(r % 512);
        v = (n < VOCAB) ? fcw[(size_t)k * VOCAB + n] : 0.f;
        h = __float2half_rn(v);
        g_wt[i] = h;
        g_wf[OFF_FC + (size_t)k * VPAD + n] = h;
        return;
    }
    size_t l = i / PL, r = i % PL;
    size_t regb; int n, k, N;
    if (r < R_CAQ) {
        regb = R_SAQKV; size_t r2 = r; N = 1536;
        n = (int)(r2 / 512); k = (int)(r2 % 512);
        v = (n < 512) ? sawq [l * 262144 + (size_t)k * 512  + n]
                      : sawkv[l * 524288 + (size_t)k * 1024 + (n - 512)];
    } else if (r < R_CAKV) {
        regb = R_CAQ; size_t r2 = r - R_CAQ; N = 512;
        n = (int)(r2 / 512); k = (int)(r2 % 512);
        v = cawq[l * 262144 + (size_t)k * 512 + n];
    } else if (r < R_SAO) {
        regb = R_CAKV; size_t r2 = r - R_CAKV; N = 1024;
        n = (int)(r2 / 512); k = (int)(r2 % 512);
        v = cawkv[l * 524288 + (size_t)k * 1024 + n];
    } else if (r < R_CAO) {
        regb = R_SAO; size_t r2 = r - R_SAO; N = 512;
        n = (int)(r2 / 512); k = (int)(r2 % 512);
        v = sawo[l * 262144 + (size_t)k * 512 + n];
    } else if (r < R_FF1) {
        regb = R_CAO; size_t r2 = r - R_CAO; N = 512;
        n = (int)(r2 / 512); k = (int)(r2 % 512);
        v = cawo[l * 262144 + (size_t)k * 512 + n];
    } else if (r < R_FF2) {
        regb = R_FF1; size_t r2 = r - R_FF1; N = 2048;
        n = (int)(r2 / 512); k = (int)(r2 % 512);
        v = ffw1[l * 1048576 + (size_t)k * 2048 + n];
    } else {
        regb = R_FF2; size_t r2 = r - R_FF2; N = 512;
        n = (int)(r2 / 2048); k = (int)(r2 % 2048);
        v = ffw2[l * 1048576 + (size_t)k * 512 + n];
    }
    h = __float2half_rn(v);
    g_wt[i] = h;
    g_wf[l * PL + regb + (size_t)k * N + n] = h;
}

__global__ void bconv_k(const float* __restrict__ boards) {
    size_t i = (size_t)blockIdx.x * blockDim.x + threadIdx.x;
    g_bf[i] = __float2half_rn(boards[i]);
}

// fcb copy + qkv-bias concat + embedding, one launch
__global__ void misc_k(const float* __restrict__ fcb,
                       const float* __restrict__ sa_bq, const float* __restrict__ sa_bkv,
                       const int* __restrict__ moves,
                       const float* __restrict__ emb, const float* __restrict__ pos) {
    size_t i = (size_t)blockIdx.x * blockDim.x + threadIdx.x;
    if (i < VPAD) g_fcb[i] = (i < VOCAB) ? fcb[i] : 0.f;
    if (i < NLAY * 1536) {
        int l = (int)(i / 1536), j = (int)(i % 1536);
        g_bqkv[i] = (j < 512) ? sa_bq[l * 512 + j] : sa_bkv[l * 1024 + (j - 512)];
    }
    if (i < (size_t)NTOK * DD) {
        int tok = (int)(i / DD), d = (int)(i % DD);
        g_x[i] = emb[(size_t)moves[tok] * DD + d] * 22.62741699796952f
               + pos[(size_t)(tok % LL) * DD + d];
    }
}

// ---------------- layernorm -> fp16 ----------------
__global__ __launch_bounds__(256) void ln_k(const float* __restrict__ X,
                                            const float* __restrict__ g,
                                            const float* __restrict__ b,
                                            __half* __restrict__ Y) {
    int row = blockIdx.x;
    const float2* x2 = (const float2*)(X + (size_t)row * DD);
    float2 v = x2[threadIdx.x];
    float s  = v.x + v.y;
    float ss = v.x * v.x + v.y * v.y;
    #pragma unroll
    for (int o = 16; o; o >>= 1) {
        s  += __shfl_down_sync(0xffffffffu, s,  o);
        ss += __shfl_down_sync(0xffffffffu, ss, o);
    }
    __shared__ float rs[8], rss[8];
    int w = threadIdx.x >> 5;
    if ((threadIdx.x & 31) == 0) { rs[w] = s; rss[w] = ss; }
    __syncthreads();
    if (threadIdx.x == 0) {
        float a = 0.f, c = 0.f;
        #pragma unroll
        for (int i = 0; i < 8; i++) { a += rs[i]; c += rss[i]; }
        rs[0] = a; rss[0] = c;
    }
    __syncthreads();
    float mean = rs[0] * (1.0f / DD);
    float var  = rss[0] * (1.0f / DD) - mean * mean;
    float rstd = rsqrtf(var + 1e-5f);
    float2 gg = ((const float2*)g)[threadIdx.x];
    float2 bb = ((const float2*)b)[threadIdx.x];
    size_t base = (size_t)row * DD + threadIdx.x * 2;
    Y[base]     = __float2half_rn((v.x - mean) * rstd * gg.x + bb.x);
    Y[base + 1] = __float2half_rn((v.y - mean) * rstd * gg.y + bb.y);
}

#if TC5
__device__ __forceinline__ uint32_t elect1() {
    uint32_t p;
    asm volatile("{\n\t.reg .pred p;\n\telect.sync _|p, 0xFFFFFFFF;\n\tselp.b32 %0, 1, 0, p;\n\t}"
                 : "=r"(p));
    return p;
}
#endif

#define MB_WAIT(mbar, ph) do {                                                        \
    uint32_t _d;                                                                      \
    do {                                                                              \
        asm volatile("{\n\t.reg .pred p;\n\t"                                         \
            "mbarrier.try_wait.parity.acquire.cta.shared::cta.b64 p, [%1], %2, 0x989680;\n\t" \
            "selp.b32 %0, 1, 0, p;\n\t}"                                              \
            : "=r"(_d) : "r"(mbar), "r"((uint32_t)(ph)) : "memory");                  \
    } while (!_d);                                                                    \
} while (0)

// SW128 K-major descriptor base: layout=SW128(2), version=1, SBO=64, LBO=1
#define DESC_BASE ((2ull<<61)|(1ull<<46)|(64ull<<32)|(1ull<<16))
// idesc kind::f16: dtype=F32, atype=btype=F16(0), N=256, M=128
#define IDESC_F16 ((1u<<4) | (32u<<17) | (8u<<24))

#define STAGE_SZ 49152                 /* A 16KB + B 32KB */
#define TG_SMEM  (1024 + 2*STAGE_SZ)   /* 99328; 2 CTAs/SM */

// ---------------- GEMM: C[M,Nc] = A[M,K] @ W, 128x256 tiles, 2-stage ----------------
// epi: 0 +bias->f32  1 relu(+bias)->f16  2 +bias+res->f32  3 +bias->f16
__global__ __launch_bounds__(128, 2) void tgemm_k(
    const __half* __restrict__ A, const __half* __restrict__ W,
    const __half* __restrict__ Wt,
    const float* __restrict__ bias, const float* __restrict__ res,
    float* __restrict__ Cf, __half* __restrict__ Ch,
    int M, int N, int K, int Nc, int epi)
{
    extern __shared__ __align__(16) char smem[];
    const int tid  = threadIdx.x;
    const int lane = tid & 31;
    const int warp = tid >> 5;
    const int m0 = blockIdx.y * 128, n0 = blockIdx.x * 256;

#if TC5
    const uint32_t sb  = (uint32_t)__cvta_generic_to_shared(smem);
    const uint32_t MB0 = sb + 16;          // two mma-done barriers
    const uint32_t SMT = sb + 1024;
    const int KT = K >> 6;

    if (warp == 0) {
        asm volatile("tcgen05.alloc.cta_group::1.sync.aligned.shared::cta.b32 [%0], 256;"
                     :: "r"(sb) : "memory");
        asm volatile("tcgen05.relinquish_alloc_permit.cta_group::1.sync.aligned;");
    }
    if (tid == 0) {
        asm volatile("mbarrier.init.shared.b64 [%0], 1;" :: "r"(MB0)     : "memory");
        asm volatile("mbarrier.init.shared.b64 [%0], 1;" :: "r"(MB0 + 8) : "memory");
    }
    __syncthreads();
    uint32_t tmem;
    asm volatile("ld.shared.b32 %0, [%1];" : "=r"(tmem) : "r"(sb));

    const __half* Ab = A  + (size_t)m0 * K;
    const __half* Bb = Wt + (size_t)n0 * K;
    const uint32_t goB2 = (uint32_t)(K << 7);   // +128 rows (halves)

    // hoisted per-thread load geometry (A: 1024 chunks; B reuses pattern x2)
    uint32_t swo[8], go[8];
    #pragma unroll
    for (int i = 0; i < 8; i++) {
        int c = tid + i * 128;
        int row = c >> 3, cb = (c & 7) << 4;
        int bo = (row << 7) + cb;
        swo[i] = (uint32_t)(bo ^ ((bo >> 3) & 0x70));
        go[i]  = (uint32_t)(row * K + (cb >> 1));
    }

    #define LOADT(kt, s) do {                                                         \
        const __half* aP = Ab + (kt) * 64;                                            \
        const __half* bP = Bb + (kt) * 64;                                            \
        uint32_t baA = SMT + (s) * STAGE_SZ, baB = baA + 16384;                       \
        _Pragma("unroll")                                                             \
        for (int i = 0; i < 8; i++) {                                                 \
            asm volatile("cp.async.cg.shared.global [%0], [%1], 16;"                  \
                :: "r"(baA + swo[i]), "l"((const void*)(aP + go[i])) : "memory");     \
            asm volatile("cp.async.cg.shared.global [%0], [%1], 16;"                  \
                :: "r"(baB + swo[i]), "l"((const void*)(bP + go[i])) : "memory");     \
            asm volatile("cp.async.cg.shared.global [%0], [%1], 16;"                  \
                :: "r"(baB + 16384 + swo[i]), "l"((const void*)(bP + goB2 + go[i])) : "memory"); \
        }                                                                             \
        asm volatile("cp.async.commit_group;" ::: "memory");                          \
    } while (0)

    LOADT(0, 0);
    if (KT > 1) LOADT(1, 1);

    for (int kt = 0; kt < KT; kt++) {
        if (kt + 1 < KT) asm volatile("cp.async.wait_group 1;" ::: "memory");
        else             asm volatile("cp.async.wait_group 0;" ::: "memory");
        asm volatile("fence.proxy.async.shared::cta;" ::: "memory");
        __syncthreads();
        if (warp == 0 && elect1()) {
            uint32_t base = SMT + (kt & 1) * STAGE_SZ;
            uint64_t ad = DESC_BASE | (uint64_t)((base >> 4) & 0x3FFF);
            uint64_t bd = DESC_BASE | (uint64_t)(((base + 16384) >> 4) & 0x3FFF);
            #pragma unroll
            for (int s = 0; s < 4; s++) {
                uint32_t en = (kt > 0 || s > 0) ? 1u : 0u;
                asm volatile(
                    "{\n\t.reg .pred p;\n\tsetp.ne.u32 p, %5, 0;\n\t"
                    "tcgen05.mma.cta_group::1.kind::f16 [%0], %1, %2, %3, {%4,%4,%4,%4}, p;\n\t}"
                    :: "r"(tmem), "l"(ad + s * 2), "l"(bd + s * 2),
                       "r"(IDESC_F16), "r"(0u), "r"(en) : "memory");
            }
            asm volatile(
                "tcgen05.commit.cta_group::1.mbarrier::arrive::one.shared::cluster.b64 [%0];"
                :: "r"(MB0 + (uint32_t)(kt & 1) * 8) : "memory");
        }
        if (kt + 2 < KT) {
            // reuse stage (kt&1): wait mma kt complete (covered by co-resident CTA)
            MB_WAIT(MB0 + (uint32_t)(kt & 1) * 8, (uint32_t)((kt >> 1) & 1));
            LOADT(kt + 2, kt & 1);
        }
    }
    {
        int j = KT - 1;
        MB_WAIT(MB0 + (uint32_t)(j & 1) * 8, (uint32_t)((j >> 1) & 1));
    }
    asm volatile("tcgen05.fence::after_thread_sync;" ::: "memory");
    __syncthreads();

    // ---- epilogue: 64-col chunks staged in smem (overlays stages), vectorized ----
    float* osm = (float*)(smem + 1024);          // [128][66]
    for (int cb = 0; cb < 256; cb += 64) {
        uint32_t d0[32], d1[32];
        asm volatile(
            "tcgen05.ld.sync.aligned.32x32b.x32.b32 "
            "{%0,%1,%2,%3,%4,%5,%6,%7,%8,%9,%10,%11,%12,%13,%14,%15,"
            "%16,%17,%18,%19,%20,%21,%22,%23,%24,%25,%26,%27,%28,%29,%30,%31}, [%32];"
            : "=r"(d0[0]),"=r"(d0[1]),"=r"(d0[2]),"=r"(d0[3]),"=r"(d0[4]),"=r"(d0[5]),
              "=r"(d0[6]),"=r"(d0[7]),"=r"(d0[8]),"=r"(d0[9]),"=r"(d0[10]),"=r"(d0[11]),
              "=r"(d0[12]),"=r"(d0[13]),"=r"(d0[14]),"=r"(d0[15]),"=r"(d0[16]),"=r"(d0[17]),
              "=r"(d0[18]),"=r"(d0[19]),"=r"(d0[20]),"=r"(d0[21]),"=r"(d0[22]),"=r"(d0[23]),
              "=r"(d0[24]),"=r"(d0[25]),"=r"(d0[26]),"=r"(d0[27]),"=r"(d0[28]),"=r"(d0[29]),
              "=r"(d0[30]),"=r"(d0[31])
            : "r"(tmem + cb));
        asm volatile(
            "tcgen05.ld.sync.aligned.32x32b.x32.b32 "
            "{%0,%1,%2,%3,%4,%5,%6,%7,%8,%9,%10,%11,%12,%13,%14,%15,"
            "%16,%17,%18,%19,%20,%21,%22,%23,%24,%25,%26,%27,%28,%29,%30,%31}, [%32];"
            : "=r"(d1[0]),"=r"(d1[1]),"=r"(d1[2]),"=r"(d1[3]),"=r"(d1[4]),"=r"(d1[5]),
              "=r"(d1[6]),"=r"(d1[7]),"=r"(d1[8]),"=r"(d1[9]),"=r"(d1[10]),"=r"(d1[11]),
              "=r"(d1[12]),"=r"(d1[13]),"=r"(d1[14]),"=r"(d1[15]),"=r"(d1[16]),"=r"(d1[17]),
              "=r"(d1[18]),"=r"(d1[19]),"=r"(d1[20]),"=r"(d1[21]),"=r"(d1[22]),"=r"(d1[23]),
              "=r"(d1[24]),"=r"(d1[25]),"=r"(d1[26]),"=r"(d1[27]),"=r"(d1[28]),"=r"(d1[29]),
              "=r"(d1[30]),"=r"(d1[31])
            : "r"(tmem + cb + 32));
        asm volatile("tcgen05.wait::ld.sync.aligned;" ::: "memory");
        float* rowp = osm + tid * 66;
        #pragma unroll
        for (int c = 0; c < 32; c++) { rowp[c] = __uint_as_float(d0[c]); rowp[32 + c] = __uint_as_float(d1[c]); }
        __syncthreads();
        const int colb = n0 + cb;
        const int c2 = lane * 2;
        if (colb + 64 <= Nc) {
            float b0 = bias[colb + c2], b1 = bias[colb + c2 + 1];
            for (int rr = warp; rr < 128; rr += 4) {
                float v0 = osm[rr * 66 + c2] + b0;
                float v1 = osm[rr * 66 + c2 + 1] + b1;
                size_t off = (size_t)(m0 + rr) * Nc + colb + c2;
                if (epi == 2) {
                    float2 rv = *(const float2*)(res + off);
                    *(float2*)(Cf + off) = make_float2(v0 + rv.x, v1 + rv.y);
                } else if (epi == 0) {
                    *(float2*)(Cf + off) = make_float2(v0, v1);
                } else {
                    if (epi == 1) { v0 = fmaxf(v0, 0.f); v1 = fmaxf(v1, 0.f); }
                    *(__half2*)(Ch + off) = __floats2half2_rn(v0, v1);
                }
            }
        } else {
            for (int rr = warp; rr < 128; rr += 4) {
                #pragma unroll
                for (int q = 0; q < 2; q++) {
                    int c = colb + c2 + q;
                    if (c < Nc) {
                        float v = osm[rr * 66 + c2 + q] + bias[c];
                        size_t off = (size_t)(m0 + rr) * Nc + c;
                        if (epi == 2)      Cf[off] = v + res[off];
                        else if (epi == 0) Cf[off] = v;
                        else if (epi == 1) Ch[off] = __float2half_rn(fmaxf(v, 0.f));
                        else               Ch[off] = __float2half_rn(v);
                    }
                }
            }
        }
        __syncthreads();
    }

    if (tid == 0) {
        asm volatile("mbarrier.inval.shared.b64 [%0];" :: "r"(MB0)     : "memory");
        asm volatile("mbarrier.inval.shared.b64 [%0];" :: "r"(MB0 + 8) : "memory");
    }
    __syncthreads();
    if (warp == 0)
        asm volatile("tcgen05.dealloc.cta_group::1.sync.aligned.b32 %0, 256;" :: "r"(tmem));
    #undef LOADT

#else
    // ================= mma.sync fallback: two 128-wide halves per tile =================
    __half* AsB = (__half*)smem;              // [2][128][40] -- 4 warps variant
    __half* WsB = (__half*)(smem + 20480);    // [2][32][136]
    #define ASO(s,r,c) (((s)*128+(r))*40+(c))
    #define WSO(s,r,c) (((s)*32+(r))*136+(c))
    const int wm = (warp & 1) * 64;
    const int wn = (warp >> 1) * 64;          // 4 warps: 2x2 of 64x64
    const int KT2 = K >> 5;

    for (int nh = 0; nh < 2; nh++) {
        int n0h = n0 + nh * 128;
        __syncthreads();
        const int arow = tid, acol = 0;       // 128 threads: each loads a 32-half row in 2 chunks
        const int wrow = tid >> 2, wcol = (tid & 3) * 32;
        const __half* Abase = A + (size_t)(m0 + arow) * K;
        const __half* Wbase = W + (size_t)wrow * N + n0h + wcol;
        float acc[4][8][4];
        #pragma unroll
        for (int i = 0; i < 4; i++)
            #pragma unroll
            for (int j = 0; j < 8; j++)
                #pragma unroll
                for (int q = 0; q < 4; q++) acc[i][j][q] = 0.f;

        #define LOAD_STAGE(s, kt) do {                                                   \
            unsigned da = (unsigned)__cvta_generic_to_shared(&AsB[ASO(s, arow, acol)]);  \
            const __half* sa = Abase + (kt) * 32;                                        \
            asm volatile("cp.async.cg.shared.global [%0], [%1], 16;\n"                   \
                         "cp.async.cg.shared.global [%2], [%3], 16;"                     \
                         :: "r"(da), "l"(sa), "r"(da + 16), "l"(sa + 8));                \
            unsigned dw = (unsigned)__cvta_generic_to_shared(&WsB[WSO(s, wrow, wcol)]);  \
            const __half* sw = Wbase + (size_t)((kt) * 32) * N;                          \
            asm volatile("cp.async.cg.shared.global [%0], [%1], 16;\n"                   \
                         "cp.async.cg.shared.global [%2], [%3], 16;\n"                   \
                         "cp.async.cg.shared.global [%4], [%5], 16;\n"                   \
                         "cp.async.cg.shared.global [%6], [%7], 16;"                     \
                         :: "r"(dw), "l"(sw), "r"(dw + 16), "l"(sw + 8),                 \
                            "r"(dw + 32), "l"(sw + 16), "r"(dw + 48), "l"(sw + 24));     \
        } while (0)

        LOAD_STAGE(0, 0);
        asm volatile("cp.async.commit_group;");
        int buf = 0;
        for (int kt = 0; kt < KT2; kt++) {
            if (kt + 1 < KT2) LOAD_STAGE(buf ^ 1, kt + 1);
            asm volatile("cp.async.commit_group;");
            asm volatile("cp.async.wait_group 1;");
            __syncthreads();
            #pragma unroll
            for (int ks = 0; ks < 2; ks++) {
                unsigned aF[4][4], bF[8][2];
                #pragma unroll
                for (int mt = 0; mt < 4; mt++) {
                    unsigned addr = (unsigned)__cvta_generic_to_shared(
                        &AsB[ASO(buf, wm + mt * 16 + (lane & 15), ks * 16 + (lane >> 4) * 8)]);
                    asm volatile("ldmatrix.sync.aligned.m8n8.x4.shared.b16 {%0,%1,%2,%3}, [%4];"
                        : "=r"(aF[mt][0]), "=r"(aF[mt][1]), "=r"(aF[mt][2]), "=r"(aF[mt][3])
                        : "r"(addr));
                }
                #pragma unroll
                for (int nt2 = 0; nt2 < 8; nt2++) {
                    unsigned addr = (unsigned)__cvta_generic_to_shared(
                        &WsB[WSO(buf, ks * 16 + (lane & 15), wn + nt2 * 8)]);
                    asm volatile("ldmatrix.sync.aligned.m8n8.x2.trans.shared.b16 {%0,%1}, [%2];"
                        : "=r"(bF[nt2][0]), "=r"(bF[nt2][1]) : "r"(addr));
                }
                #pragma unroll
                for (int mt = 0; mt < 4; mt++)
                    #pragma unroll
                    for (int nt2 = 0; nt2 < 8; nt2++) {
                        asm volatile(
                            "mma.sync.aligned.m16n8k16.row.col.f32.f16.f16.f32 "
                            "{%0,%1,%2,%3}, {%4,%5,%6,%7}, {%8,%9}, {%0,%1,%2,%3};"
                            : "+f"(acc[mt][nt2][0]), "+f"(acc[mt][nt2][1]),
                              "+f"(acc[mt][nt2][2]), "+f"(acc[mt][nt2][3])
                            : "r"(aF[mt][0]), "r"(aF[mt][1]), "r"(aF[mt][2]), "r"(aF[mt][3]),
                              "r"(bF[nt2][0]), "r"(bF[nt2][1]));
                    }
            }
            buf ^= 1;
            __syncthreads();
        }
        #pragma unroll
        for (int mt = 0; mt < 4; mt++) {
            int r0 = m0 + wm + mt * 16 + (lane >> 2);
            #pragma unroll
            for (int nt2 = 0; nt2 < 8; nt2++) {
                int c0 = n0h + wn + nt2 * 8 + (lane & 3) * 2;
                #pragma unroll
                for (int q = 0; q < 4; q++) {
                    int rr = r0 + (q >> 1) * 8;
                    int c = c0 + (q & 1);
                    if (c < Nc) {
                        float v = acc[mt][nt2][q] + bias[c];
                        size_t off = (size_t)rr * Nc + c;
                        if (epi == 0)      Cf[off] = v;
                        else if (epi == 1) Ch[off] = __float2half_rn(fmaxf(v, 0.f));
                        else if (epi == 2) Cf[off] = v + res[off];
                        else               Ch[off] = __float2half_rn(v);
                    }
                }
            }
        }
        #undef LOAD_STAGE
    }
    #undef ASO
    #undef WSO
#endif
}

// ---------------- self attention: per (b,h), QKV packed rows of 1536 ----------------
__global__ __launch_bounds__(128) void selfattn_k(const __half* __restrict__ QKV,
                                                  const int* __restrict__ lengths,
                                                  __half* __restrict__ O) {
    int b = blockIdx.x, h = blockIdx.y;
    __shared__ float q[LL][65], k[LL][65], v[LL][65], s[LL][11];
    int tid = threadIdx.x;
    int len = lengths[b];
    for (int idx = tid; idx < LL * 64; idx += 128) {
        int i = idx >> 6, d = idx & 63;
        size_t base = ((size_t)(b * LL + i)) * 1536 + h * 64 + d;
        q[i][d] = __half2float(QKV[base]);
        k[i][d] = __half2float(QKV[base + 512]);
        v[i][d] = __half2float(QKV[base + 1024]);
    }
    __syncthreads();
    for (int idx = tid; idx < LL * LL; idx += 128) {
        int i = idx / LL, j = idx % LL;
        float acc = 0.f;
        #pragma unroll
        for (int d = 0; d < 64; d++) acc += q[i][d] * k[j][d];
        acc *= 0.125f;
        if (j > i || j >= len) acc = -1e30f;
        s[i][j] = acc;
    }
    __syncthreads();
    if (tid < LL) {
        float mx = -1e30f;
        #pragma unroll
        for (int j = 0; j < LL; j++) mx = fmaxf(mx, s[tid][j]);
        float sum = 0.f;
        #pragma unroll
        for (int j = 0; j < LL; j++) { float e = expf(s[tid][j] - mx); s[tid][j] = e; sum += e; }
        float inv = 1.0f / sum;
        #pragma unroll
        for (int j = 0; j < LL; j++) s[tid][j] *= inv;
    }
    __syncthreads();
    for (int idx = tid; idx < LL * 64; idx += 128) {
        int i = idx >> 6, d = idx & 63;
        float acc = 0.f;
        #pragma unroll
        for (int j = 0; j < LL; j++) acc += s[i][j] * v[j][d];
        O[((size_t)(b * LL + i)) * DD + h * 64 + d] = __float2half_rn(acc);
    }
}

// ---------------- cross attention: per (b,h), Lq=10, Lk=70 ----------------
__global__ __launch_bounds__(256) void crossattn_k(const __half* __restrict__ Q,
                                                   const __half* __restrict__ CKV,
                                                   __half* __restrict__ O) {
    int b = blockIdx.x, h = blockIdx.y;
    __shared__ float q[LL][65], kk[BOARD][65], vv[BOARD][65], s[LL][71];
    int tid = threadIdx.x;
    for (int idx = tid; idx < LL * 64; idx += 256) {
        int i = idx >> 6, d = idx & 63;
        q[i][d] = __half2float(Q[((size_t)(b * LL + i)) * DD + h * 64 + d]);
    }
    for (int idx = tid; idx < BOARD * 64; idx += 256) {
        int j = idx >> 6, d = idx & 63;
        size_t off = ((size_t)(b * BOARD + j)) * 1024 + h * 64 + d;
        kk[j][d] = __half2float(CKV[off]);
        vv[j][d] = __half2float(CKV[off + 512]);
    }
    __syncthreads();
    for (int idx = tid; idx < LL * BOARD; idx += 256) {
        int i = idx / BOARD, j = idx % BOARD;
        float acc = 0.f;
        #pragma unroll
        for (int d = 0; d < 64; d++) acc += q[i][d] * kk[j][d];
        s[i][j] = acc * 0.125f;
    }
    __syncthreads();
    if (tid < LL) {
        float mx = -1e30f;
        for (int j = 0; j < BOARD; j++) mx = fmaxf(mx, s[tid][j]);
        float sum = 0.f;
        for (int j = 0; j < BOARD; j++) { float e = expf(s[tid][j] - mx); s[tid][j] = e; sum += e; }
        float inv = 1.0f / sum;
        for (int j = 0; j < BOARD; j++) s[tid][j] *= inv;
    }
    __syncthreads();
    for (int idx = tid; idx < LL * 64; idx += 256) {
        int i = idx >> 6, d = idx & 63;
        float acc = 0.f;
        #pragma unroll
        for (int j = 0; j < BOARD; j++) acc += s[i][j] * vv[j][d];
        O[((size_t)(b * LL + i)) * DD + h * 64 + d] = __float2half_rn(acc);
    }
}

// ---------------- host ----------------
static __half *s_wf, *s_wt;

static void tgemm(const __half* A, size_t woff, const float* bias, const float* res,
                  float* Cf, __half* Ch, int M, int N, int K, int Nc, int epi) {
    dim3 grid(N / 256, M / 128);
    tgemm_k<<<grid, 128, TG_SMEM>>>(A, s_wf + woff, s_wt + woff, bias, res, Cf, Ch,
                                    M, N, K, Nc, epi);
}

extern "C" void kernel_launch(void* const* d_in, const int* in_sizes, int n_in,
                              void* d_out, int out_size) {
    const int*   moves   = (const int*)d_in[0];
    const int*   lengths = (const int*)d_in[1];
    const float* boards  = (const float*)d_in[2];
    const float* emb     = (const float*)d_in[3];
    const float* pos     = (const float*)d_in[4];
    const float* sa_ln_g = (const float*)d_in[5];
    const float* sa_ln_b = (const float*)d_in[6];
    const float* sa_wq   = (const float*)d_in[7];
    const float* sa_bq   = (const float*)d_in[8];
    const float* sa_wkv  = (const float*)d_in[9];
    const float* sa_bkv  = (const float*)d_in[10];
    const float* sa_wo   = (const float*)d_in[11];
    const float* sa_bo   = (const float*)d_in[12];
    const float* ca_ln_g = (const float*)d_in[13];
    const float* ca_ln_b = (const float*)d_in[14];
    const float* ca_wq   = (const float*)d_in[15];
    const float* ca_bq   = (const float*)d_in[16];
    const float* ca_wkv  = (const float*)d_in[17];
    const float* ca_bkv  = (const float*)d_in[18];
    const float* ca_wo   = (const float*)d_in[19];
    const float* ca_bo   = (const float*)d_in[20];
    const float* ff_ln_g = (const float*)d_in[21];
    const float* ff_ln_b = (const float*)d_in[22];
    const float* ff_w1   = (const float*)d_in[23];
    const float* ff_b1   = (const float*)d_in[24];
    const float* ff_w2   = (const float*)d_in[25];
    const float* ff_b2   = (const float*)d_in[26];
    const float* fin_g   = (const float*)d_in[27];
    const float* fin_b   = (const float*)d_in[28];
    const float* fc_w    = (const float*)d_in[29];
    const float* fc_b    = (const float*)d_in[30];
    float* out = (float*)d_out;

    cudaFuncSetAttribute(tgemm_k, cudaFuncAttributeMaxDynamicSharedMemorySize, TG_SMEM);

    float *px, *pfcb, *pbqkv;
    __half *pxn, *pq, *pqkv, *pao, *ph, *pckv, *pbf;
    cudaGetSymbolAddress((void**)&px,    g_x);
    cudaGetSymbolAddress((void**)&pfcb,  g_fcb);
    cudaGetSymbolAddress((void**)&pbqkv, g_bqkv);
    cudaGetSymbolAddress((void**)&pxn,   g_xn);
    cudaGetSymbolAddress((void**)&pq,    g_q);
    cudaGetSymbolAddress((void**)&pqkv,  g_qkv);
    cudaGetSymbolAddress((void**)&pao,   g_ao);
    cudaGetSymbolAddress((void**)&ph,    g_h);
    cudaGetSymbolAddress((void**)&pckv,  g_ckv);
    cudaGetSymbolAddress((void**)&pbf,   g_bf);
    cudaGetSymbolAddress((void**)&s_wf,  g_wf);
    cudaGetSymbolAddress((void**)&s_wt,  g_wt);

    // prep: 3 launches; launch #4 = layer-0 caKV (the ncu target)
    wprep_k<<<(unsigned)((WTOT + 511) / 512), 512>>>(sa_wq, sa_wkv, sa_wo, ca_wq, ca_wkv,
                                                     ca_wo, ff_w1, ff_w2, fc_w);
    bconv_k<<<(unsigned)(((size_t)NBRD * DD) / 512), 512>>>(boards);
    misc_k<<<(NTOK * DD) / 512, 512>>>(fc_b, sa_bq, sa_bkv, moves, emb, pos);

    // layer-0 cross-KV (depends only on boards) hoisted
    tgemm(pbf, R_CAKV, ca_bkv, nullptr, nullptr, pckv, NBRD, 1024, 512, 1024, 3);

    for (int i = 0; i < NLAY; i++) {
        size_t WB = (size_t)i * PL;

        // ---- self attention ----
        ln_k<<<NTOK, 256>>>(px, sa_ln_g + i * DD, sa_ln_b + i * DD, pxn);
        tgemm(pxn, WB + R_SAQKV, pbqkv + i * 1536, nullptr, nullptr, pqkv,
              NTOK, 1536, 512, 1536, 3);
        selfattn_k<<<dim3(BB, HH), 128>>>(pqkv, lengths, pao);
        tgemm(pao, WB + R_SAO, sa_bo + i * DD, px, px, nullptr,
              NTOK, 512, 512, 512, 2);

        // ---- cross attention ----
        ln_k<<<NTOK, 256>>>(px, ca_ln_g + i * DD, ca_ln_b + i * DD, pxn);
        tgemm(pxn, WB + R_CAQ, ca_bq + i * 512, nullptr, nullptr, pq,
              NTOK, 512, 512, 512, 3);
        if (i > 0)
            tgemm(pbf, WB + R_CAKV, ca_bkv + i * 1024, nullptr, nullptr, pckv,
                  NBRD, 1024, 512, 1024, 3);
        crossattn_k<<<dim3(BB, HH), 256>>>(pq, pckv, pao);
        tgemm(pao, WB + R_CAO, ca_bo + i * DD, px, px, nullptr,
              NTOK, 512, 512, 512, 2);

        // ---- FFN ----
        ln_k<<<NTOK, 256>>>(px, ff_ln_g + i * DD, ff_ln_b + i * DD, pxn);
        tgemm(pxn, WB + R_FF1, ff_b1 + i * DI, nullptr, nullptr, ph,
              NTOK, DI, 512, DI, 1);
        tgemm(ph, WB + R_FF2, ff_b2 + i * DD, px, px, nullptr,
              NTOK, 512, DI, 512, 2);
    }

    ln_k<<<NTOK, 256>>>(px, fin_g, fin_b, pxn);
    tgemm(pxn, OFF_FC, pfcb, nullptr, out, nullptr, NTOK, VPAD, 512, VOCAB, 0);
}

// round 14
// speedup vs baseline: 2.5683x; 1.7759x over previous
#include <cuda_runtime.h>
#include <cuda_fp16.h>
#include <stdint.h>
#include <math.h>

#define BB 2048
#define LL 10
#define VOCAB 1974
#define DD 512
#define HH 8
#define DI 2048
#define NLAY 6
#define BOARD 70
#define NTOK (BB*LL)       /* 20480 */
#define NBRD (BB*BOARD)    /* 143360 */
#define VPAD 2048

#if defined(__CUDA_ARCH_FEAT_SM103_ALL) || defined(__CUDA_ARCH_FEAT_SM100_ALL) || defined(__CUDA_ARCH_FEAT_SM101_ALL)
#define TC5 1
#else
#define TC5 0
#endif

// ---- weight arena: per-layer blocks, [N,K] fp16 (g_wt) ----
#define PL       4194304ull
#define R_SAQKV  0ull
#define R_CAQ    786432ull
#define R_CAKV   1048576ull
#define R_SAO    1572864ull
#define R_CAO    1835008ull
#define R_FF1    2097152ull
#define R_FF2    3145728ull
#define OFF_FC   25165824ull
#define WTOT     26214400ull

// ---------------- scratch (static device buffers) ----------------
__device__ float  g_x   [NTOK*DD];
__device__ float  g_fcb [VPAD];
__device__ float  g_bqkv[NLAY*1536];
__device__ __half g_xn  [NTOK*DD];
__device__ __half g_q   [NTOK*DD];
__device__ __half g_qkv [NTOK*1536];
__device__ __half g_ao  [NTOK*DD];
__device__ __half g_h   [NTOK*DI];
__device__ __half g_ckv [(size_t)NBRD*1024];
__device__ __half g_bf  [(size_t)NBRD*DD];
__device__ __half g_wt  [WTOT];    // [N,K]  (tcgen05)

// ---------------- prep: weights -> [N,K] fp16 (one launch, coalesced writes) ----------------
__global__ void wprep_k(const float* __restrict__ sawq, const float* __restrict__ sawkv,
                        const float* __restrict__ sawo, const float* __restrict__ cawq,
                        const float* __restrict__ cawkv, const float* __restrict__ cawo,
                        const float* __restrict__ ffw1, const float* __restrict__ ffw2,
                        const float* __restrict__ fcw) {
    size_t i = (size_t)blockIdx.x * blockDim.x + threadIdx.x;
    if (i >= WTOT) return;
    float v;
    if (i >= OFF_FC) {
        size_t r = i - OFF_FC;
        int n = (int)(r / 512), k = (int)(r % 512);
        v = (n < VOCAB) ? fcw[(size_t)k * VOCAB + n] : 0.f;
        g_wt[i] = __float2half_rn(v);
        return;
    }
    size_t l = i / PL, r = i % PL;
    int n, k;
    if (r < R_CAQ) {
        size_t r2 = r;
        n = (int)(r2 / 512); k = (int)(r2 % 512);
        v = (n < 512) ? sawq [l * 262144 + (size_t)k * 512  + n]
                      : sawkv[l * 524288 + (size_t)k * 1024 + (n - 512)];
    } else if (r < R_CAKV) {
        size_t r2 = r - R_CAQ;
        n = (int)(r2 / 512); k = (int)(r2 % 512);
        v = cawq[l * 262144 + (size_t)k * 512 + n];
    } else if (r < R_SAO) {
        size_t r2 = r - R_CAKV;
        n = (int)(r2 / 512); k = (int)(r2 % 512);
        v = cawkv[l * 524288 + (size_t)k * 1024 + n];
    } else if (r < R_CAO) {
        size_t r2 = r - R_SAO;
        n = (int)(r2 / 512); k = (int)(r2 % 512);
        v = sawo[l * 262144 + (size_t)k * 512 + n];
    } else if (r < R_FF1) {
        size_t r2 = r - R_CAO;
        n = (int)(r2 / 512); k = (int)(r2 % 512);
        v = cawo[l * 262144 + (size_t)k * 512 + n];
    } else if (r < R_FF2) {
        size_t r2 = r - R_FF1;
        n = (int)(r2 / 512); k = (int)(r2 % 512);
        v = ffw1[l * 1048576 + (size_t)k * 2048 + n];
    } else {
        size_t r2 = r - R_FF2;
        n = (int)(r2 / 2048); k = (int)(r2 % 2048);
        v = ffw2[l * 1048576 + (size_t)k * 512 + n];
    }
    g_wt[i] = __float2half_rn(v);
}

__global__ void bconv_k(const float* __restrict__ boards) {
    size_t i = (size_t)blockIdx.x * blockDim.x + threadIdx.x;
    g_bf[i] = __float2half_rn(boards[i]);
}

// fcb copy + qkv-bias concat + embedding, one launch
__global__ void misc_k(const float* __restrict__ fcb,
                       const float* __restrict__ sa_bq, const float* __restrict__ sa_bkv,
                       const int* __restrict__ moves,
                       const float* __restrict__ emb, const float* __restrict__ pos) {
    size_t i = (size_t)blockIdx.x * blockDim.x + threadIdx.x;
    if (i < VPAD) g_fcb[i] = (i < VOCAB) ? fcb[i] : 0.f;
    if (i < NLAY * 1536) {
        int l = (int)(i / 1536), j = (int)(i % 1536);
        g_bqkv[i] = (j < 512) ? sa_bq[l * 512 + j] : sa_bkv[l * 1024 + (j - 512)];
    }
    if (i < (size_t)NTOK * DD) {
        int tok = (int)(i / DD), d = (int)(i % DD);
        g_x[i] = emb[(size_t)moves[tok] * DD + d] * 22.62741699796952f
               + pos[(size_t)(tok % LL) * DD + d];
    }
}

// ---------------- layernorm -> fp16 ----------------
__global__ __launch_bounds__(256) void ln_k(const float* __restrict__ X,
                                            const float* __restrict__ g,
                                            const float* __restrict__ b,
                                            __half* __restrict__ Y) {
    int row = blockIdx.x;
    const float2* x2 = (const float2*)(X + (size_t)row * DD);
    float2 v = x2[threadIdx.x];
    float s  = v.x + v.y;
    float ss = v.x * v.x + v.y * v.y;
    #pragma unroll
    for (int o = 16; o; o >>= 1) {
        s  += __shfl_down_sync(0xffffffffu, s,  o);
        ss += __shfl_down_sync(0xffffffffu, ss, o);
    }
    __shared__ float rs[8], rss[8];
    int w = threadIdx.x >> 5;
    if ((threadIdx.x & 31) == 0) { rs[w] = s; rss[w] = ss; }
    __syncthreads();
    if (threadIdx.x == 0) {
        float a = 0.f, c = 0.f;
        #pragma unroll
        for (int i = 0; i < 8; i++) { a += rs[i]; c += rss[i]; }
        rs[0] = a; rss[0] = c;
    }
    __syncthreads();
    float mean = rs[0] * (1.0f / DD);
    float var  = rss[0] * (1.0f / DD) - mean * mean;
    float rstd = rsqrtf(var + 1e-5f);
    float2 gg = ((const float2*)g)[threadIdx.x];
    float2 bb = ((const float2*)b)[threadIdx.x];
    size_t base = (size_t)row * DD + threadIdx.x * 2;
    Y[base]     = __float2half_rn((v.x - mean) * rstd * gg.x + bb.x);
    Y[base + 1] = __float2half_rn((v.y - mean) * rstd * gg.y + bb.y);
}

#if TC5
__device__ __forceinline__ uint32_t elect1() {
    uint32_t p;
    asm volatile("{\n\t.reg .pred p;\n\telect.sync _|p, 0xFFFFFFFF;\n\tselp.b32 %0, 1, 0, p;\n\t}"
                 : "=r"(p));
    return p;
}
#endif

#define MB_WAIT(mbar, ph) do {                                                        \
    uint32_t _d;                                                                      \
    do {                                                                              \
        asm volatile("{\n\t.reg .pred p;\n\t"                                         \
            "mbarrier.try_wait.parity.acquire.cta.shared::cta.b64 p, [%1], %2, 0x989680;\n\t" \
            "selp.b32 %0, 1, 0, p;\n\t}"                                              \
            : "=r"(_d) : "r"(mbar), "r"((uint32_t)(ph)) : "memory");                  \
    } while (!_d);                                                                    \
} while (0)

// SW128 K-major descriptor base: layout=SW128(2), version=1, SBO=64, LBO=1
#define DESC_BASE ((2ull<<61)|(1ull<<46)|(64ull<<32)|(1ull<<16))
// idesc kind::f16: dtype=F32, atype=btype=F16(0), N=256, M=128
#define IDESC_F16 ((1u<<4) | (32u<<17) | (8u<<24))

#define STAGE_SZ 49152                 /* A 16KB + B 32KB */
#define TG_SMEM  (1024 + 2*STAGE_SZ)   /* 99328; 2 CTAs/SM */

// ---------------- GEMM: C[M,Nc] = A[M,K] @ Wt^T, 128x256 tiles, 2-stage ----------------
// epi: 0 +bias->f32  1 relu(+bias)->f16  2 +bias+res->f32  3 +bias->f16
__global__ __launch_bounds__(128, 2) void tgemm_k(
    const __half* __restrict__ A, const __half* __restrict__ Wt,
    const float* __restrict__ bias, const float* __restrict__ res,
    float* __restrict__ Cf, __half* __restrict__ Ch,
    int M, int N, int K, int Nc, int epi)
{
    extern __shared__ __align__(16) char smem[];
    const int tid  = threadIdx.x;
    const int lane = tid & 31;
    const int warp = tid >> 5;
    const int m0 = blockIdx.y * 128, n0 = blockIdx.x * 256;

#if TC5
    const uint32_t sb  = (uint32_t)__cvta_generic_to_shared(smem);
    const uint32_t MB0 = sb + 16;          // two mma-done barriers
    const uint32_t SMT = sb + 1024;
    const int KT = K >> 6;

    if (warp == 0) {
        asm volatile("tcgen05.alloc.cta_group::1.sync.aligned.shared::cta.b32 [%0], 256;"
                     :: "r"(sb) : "memory");
        asm volatile("tcgen05.relinquish_alloc_permit.cta_group::1.sync.aligned;");
    }
    if (tid == 0) {
        asm volatile("mbarrier.init.shared.b64 [%0], 1;" :: "r"(MB0)     : "memory");
        asm volatile("mbarrier.init.shared.b64 [%0], 1;" :: "r"(MB0 + 8) : "memory");
    }
    __syncthreads();
    uint32_t tmem;
    asm volatile("ld.shared.b32 %0, [%1];" : "=r"(tmem) : "r"(sb));

    const __half* Ab = A  + (size_t)m0 * K;
    const __half* Bb = Wt + (size_t)n0 * K;
    const uint32_t goB2 = (uint32_t)(K << 7);   // +128 rows (halves)

    uint32_t swo[8], go[8];
    #pragma unroll
    for (int i = 0; i < 8; i++) {
        int c = tid + i * 128;
        int row = c >> 3, cb = (c & 7) << 4;
        int bo = (row << 7) + cb;
        swo[i] = (uint32_t)(bo ^ ((bo >> 3) & 0x70));
        go[i]  = (uint32_t)(row * K + (cb >> 1));
    }

    #define LOADT(kt, s) do {                                                         \
        const __half* aP = Ab + (kt) * 64;                                            \
        const __half* bP = Bb + (kt) * 64;                                            \
        uint32_t baA = SMT + (s) * STAGE_SZ, baB = baA + 16384;                       \
        _Pragma("unroll")                                                             \
        for (int i = 0; i < 8; i++) {                                                 \
            asm volatile("cp.async.cg.shared.global [%0], [%1], 16;"                  \
                :: "r"(baA + swo[i]), "l"((const void*)(aP + go[i])) : "memory");     \
            asm volatile("cp.async.cg.shared.global [%0], [%1], 16;"                  \
                :: "r"(baB + swo[i]), "l"((const void*)(bP + go[i])) : "memory");     \
            asm volatile("cp.async.cg.shared.global [%0], [%1], 16;"                  \
                :: "r"(baB + 16384 + swo[i]), "l"((const void*)(bP + goB2 + go[i])) : "memory"); \
        }                                                                             \
        asm volatile("cp.async.commit_group;" ::: "memory");                          \
    } while (0)

    LOADT(0, 0);
    if (KT > 1) LOADT(1, 1);

    for (int kt = 0; kt < KT; kt++) {
        if (kt + 1 < KT) asm volatile("cp.async.wait_group 1;" ::: "memory");
        else             asm volatile("cp.async.wait_group 0;" ::: "memory");
        asm volatile("fence.proxy.async.shared::cta;" ::: "memory");
        __syncthreads();
        if (warp == 0 && elect1()) {
            uint32_t base = SMT + (kt & 1) * STAGE_SZ;
            uint64_t ad = DESC_BASE | (uint64_t)((base >> 4) & 0x3FFF);
            uint64_t bd = DESC_BASE | (uint64_t)(((base + 16384) >> 4) & 0x3FFF);
            #pragma unroll
            for (int s = 0; s < 4; s++) {
                uint32_t en = (kt > 0 || s > 0) ? 1u : 0u;
                asm volatile(
                    "{\n\t.reg .pred p;\n\tsetp.ne.u32 p, %5, 0;\n\t"
                    "tcgen05.mma.cta_group::1.kind::f16 [%0], %1, %2, %3, {%4,%4,%4,%4}, p;\n\t}"
                    :: "r"(tmem), "l"(ad + s * 2), "l"(bd + s * 2),
                       "r"(IDESC_F16), "r"(0u), "r"(en) : "memory");
            }
            asm volatile(
                "tcgen05.commit.cta_group::1.mbarrier::arrive::one.shared::cluster.b64 [%0];"
                :: "r"(MB0 + (uint32_t)(kt & 1) * 8) : "memory");
        }
        if (kt + 2 < KT) {
            MB_WAIT(MB0 + (uint32_t)(kt & 1) * 8, (uint32_t)((kt >> 1) & 1));
            LOADT(kt + 2, kt & 1);
        }
    }
    {
        int j = KT - 1;
        MB_WAIT(MB0 + (uint32_t)(j & 1) * 8, (uint32_t)((j >> 1) & 1));
    }
    asm volatile("tcgen05.fence::after_thread_sync;" ::: "memory");
    __syncthreads();

    // ---- epilogue: 64-col chunks staged in smem, vectorized coalesced stores ----
    float* osm = (float*)(smem + 1024);          // [128][66]
    for (int cb = 0; cb < 256; cb += 64) {
        uint32_t d0[32], d1[32];
        asm volatile(
            "tcgen05.ld.sync.aligned.32x32b.x32.b32 "
            "{%0,%1,%2,%3,%4,%5,%6,%7,%8,%9,%10,%11,%12,%13,%14,%15,"
            "%16,%17,%18,%19,%20,%21,%22,%23,%24,%25,%26,%27,%28,%29,%30,%31}, [%32];"
            : "=r"(d0[0]),"=r"(d0[1]),"=r"(d0[2]),"=r"(d0[3]),"=r"(d0[4]),"=r"(d0[5]),
              "=r"(d0[6]),"=r"(d0[7]),"=r"(d0[8]),"=r"(d0[9]),"=r"(d0[10]),"=r"(d0[11]),
              "=r"(d0[12]),"=r"(d0[13]),"=r"(d0[14]),"=r"(d0[15]),"=r"(d0[16]),"=r"(d0[17]),
              "=r"(d0[18]),"=r"(d0[19]),"=r"(d0[20]),"=r"(d0[21]),"=r"(d0[22]),"=r"(d0[23]),
              "=r"(d0[24]),"=r"(d0[25]),"=r"(d0[26]),"=r"(d0[27]),"=r"(d0[28]),"=r"(d0[29]),
              "=r"(d0[30]),"=r"(d0[31])
            : "r"(tmem + cb));
        asm volatile(
            "tcgen05.ld.sync.aligned.32x32b.x32.b32 "
            "{%0,%1,%2,%3,%4,%5,%6,%7,%8,%9,%10,%11,%12,%13,%14,%15,"
            "%16,%17,%18,%19,%20,%21,%22,%23,%24,%25,%26,%27,%28,%29,%30,%31}, [%32];"
            : "=r"(d1[0]),"=r"(d1[1]),"=r"(d1[2]),"=r"(d1[3]),"=r"(d1[4]),"=r"(d1[5]),
              "=r"(d1[6]),"=r"(d1[7]),"=r"(d1[8]),"=r"(d1[9]),"=r"(d1[10]),"=r"(d1[11]),
              "=r"(d1[12]),"=r"(d1[13]),"=r"(d1[14]),"=r"(d1[15]),"=r"(d1[16]),"=r"(d1[17]),
              "=r"(d1[18]),"=r"(d1[19]),"=r"(d1[20]),"=r"(d1[21]),"=r"(d1[22]),"=r"(d1[23]),
              "=r"(d1[24]),"=r"(d1[25]),"=r"(d1[26]),"=r"(d1[27]),"=r"(d1[28]),"=r"(d1[29]),
              "=r"(d1[30]),"=r"(d1[31])
            : "r"(tmem + cb + 32));
        asm volatile("tcgen05.wait::ld.sync.aligned;" ::: "memory");
        float* rowp = osm + tid * 66;
        #pragma unroll
        for (int c = 0; c < 32; c++) { rowp[c] = __uint_as_float(d0[c]); rowp[32 + c] = __uint_as_float(d1[c]); }
        __syncthreads();
        const int colb = n0 + cb;
        const int c2 = lane * 2;
        if (colb + 64 <= Nc) {
            float b0 = bias[colb + c2], b1 = bias[colb + c2 + 1];
            for (int rr = warp; rr < 128; rr += 4) {
                float v0 = osm[rr * 66 + c2] + b0;
                float v1 = osm[rr * 66 + c2 + 1] + b1;
                size_t off = (size_t)(m0 + rr) * Nc + colb + c2;
                if (epi == 2) {
                    float2 rv = *(const float2*)(res + off);
                    *(float2*)(Cf + off) = make_float2(v0 + rv.x, v1 + rv.y);
                } else if (epi == 0) {
                    *(float2*)(Cf + off) = make_float2(v0, v1);
                } else {
                    if (epi == 1) { v0 = fmaxf(v0, 0.f); v1 = fmaxf(v1, 0.f); }
                    *(__half2*)(Ch + off) = __floats2half2_rn(v0, v1);
                }
            }
        } else {
            for (int rr = warp; rr < 128; rr += 4) {
                #pragma unroll
                for (int q = 0; q < 2; q++) {
                    int c = colb + c2 + q;
                    if (c < Nc) {
                        float v = osm[rr * 66 + c2 + q] + bias[c];
                        size_t off = (size_t)(m0 + rr) * Nc + c;
                        if (epi == 2)      Cf[off] = v + res[off];
                        else if (epi == 0) Cf[off] = v;
                        else if (epi == 1) Ch[off] = __float2half_rn(fmaxf(v, 0.f));
                        else               Ch[off] = __float2half_rn(v);
                    }
                }
            }
        }
        __syncthreads();
    }

    if (tid == 0) {
        asm volatile("mbarrier.inval.shared.b64 [%0];" :: "r"(MB0)     : "memory");
        asm volatile("mbarrier.inval.shared.b64 [%0];" :: "r"(MB0 + 8) : "memory");
    }
    __syncthreads();
    if (warp == 0)
        asm volatile("tcgen05.dealloc.cta_group::1.sync.aligned.b32 %0, 256;" :: "r"(tmem));
    #undef LOADT

#else
    // ===== naive fallback (never executed on sm_103a; kept for non-'a' pass validity) =====
    for (int idx = tid; idx < 128 * 256; idx += 128) {
        int m = m0 + idx / 256;
        int n = n0 + (idx % 256);
        if (m < M && n < Nc) {
            float acc = bias[n];
            const __half* ap = A + (size_t)m * K;
            const __half* wp = Wt + (size_t)n * K;
            for (int k = 0; k < K; k++) acc += __half2float(ap[k]) * __half2float(wp[k]);
            size_t off = (size_t)m * Nc + n;
            if (epi == 0)      Cf[off] = acc;
            else if (epi == 1) Ch[off] = __float2half_rn(fmaxf(acc, 0.f));
            else if (epi == 2) Cf[off] = acc + res[off];
            else               Ch[off] = __float2half_rn(acc);
        }
    }
#endif
}

// ---------------- self attention v2: per (b,h), half2 smem, 128 threads ----------------
__global__ __launch_bounds__(128) void selfattn_k(const __half* __restrict__ QKV,
                                                  const int* __restrict__ lengths,
                                                  __half* __restrict__ O) {
    int b = blockIdx.x, h = blockIdx.y;
    __shared__ __half2 qs[LL][33], ks[LL][33], vs[LL][33];
    __shared__ float s[LL][12];
    int tid = threadIdx.x;
    int len = lengths[b];
    const __half2* base = (const __half2*)QKV + ((size_t)b * LL) * 768 + h * 32;
    for (int idx = tid; idx < LL * 32; idx += 128) {
        int i = idx >> 5, d2 = idx & 31;
        const __half2* rp = base + (size_t)i * 768 + d2;
        qs[i][d2] = rp[0];
        ks[i][d2] = rp[256];
        vs[i][d2] = rp[512];
    }
    __syncthreads();
    for (int idx = tid; idx < LL * LL; idx += 128) {
        int i = idx / LL, j = idx % LL;
        float acc = 0.f;
        if (j <= i && j < len) {
            #pragma unroll
            for (int d2 = 0; d2 < 32; d2++) {
                float2 qv = __half22float2(qs[i][d2]);
                float2 kv = __half22float2(ks[j][d2]);
                acc += qv.x * kv.x + qv.y * kv.y;
            }
            acc *= 0.125f;
        } else acc = -1e30f;
        s[i][j] = acc;
    }
    __syncthreads();
    if (tid < LL) {
        float mx = -1e30f;
        #pragma unroll
        for (int j = 0; j < LL; j++) mx = fmaxf(mx, s[tid][j]);
        float sum = 0.f;
        #pragma unroll
        for (int j = 0; j < LL; j++) { float e = expf(s[tid][j] - mx); s[tid][j] = e; sum += e; }
        float inv = 1.0f / sum;
        #pragma unroll
        for (int j = 0; j < LL; j++) s[tid][j] *= inv;
    }
    __syncthreads();
    __half2* ob = (__half2*)O + ((size_t)b * LL) * 256 + h * 32;
    for (int idx = tid; idx < LL * 32; idx += 128) {
        int i = idx >> 5, d2 = idx & 31;
        float ax = 0.f, ay = 0.f;
        #pragma unroll
        for (int j = 0; j < LL; j++) {
            float sv = s[i][j];
            float2 vv = __half22float2(vs[j][d2]);
            ax += sv * vv.x; ay += sv * vv.y;
        }
        ob[(size_t)i * 256 + d2] = __floats2half2_rn(ax, ay);
    }
}

// ---------------- cross attention v2: per (b,h), half2 smem, 256 threads ----------------
__global__ __launch_bounds__(256) void crossattn_k(const __half* __restrict__ Q,
                                                   const __half* __restrict__ CKV,
                                                   __half* __restrict__ O) {
    int b = blockIdx.x, h = blockIdx.y;
    __shared__ __half2 qs[LL][33];
    __shared__ __half2 ks[BOARD][33], vs[BOARD][33];
    __shared__ float s[LL][72];
    int tid = threadIdx.x;

    // loads (coalesced half2)
    const __half2* qb = (const __half2*)Q + ((size_t)b * LL) * 256 + h * 32;
    for (int idx = tid; idx < LL * 32; idx += 256) {
        int i = idx >> 5, d2 = idx & 31;
        qs[i][d2] = qb[(size_t)i * 256 + d2];
    }
    const __half2* cb = (const __half2*)CKV + ((size_t)b * BOARD) * 512 + h * 32;
    for (int idx = tid; idx < BOARD * 32; idx += 256) {
        int j = idx >> 5, d2 = idx & 31;
        const __half2* rp = cb + (size_t)j * 512 + d2;
        ks[j][d2] = rp[0];
        vs[j][d2] = rp[256];
    }
    __syncthreads();

    // scores: thread handles (i, 4 consecutive j)
    {
        int idx = tid;                 // 10 * 18 = 180 work items
        if (idx < 180) {
            int i = idx / 18, g = idx % 18;
            int j0 = g * 4;
            float a0 = 0.f, a1 = 0.f, a2 = 0.f, a3 = 0.f;
            #pragma unroll
            for (int d2 = 0; d2 < 32; d2++) {
                float2 qv = __half22float2(qs[i][d2]);
                float2 k0 = __half22float2(ks[j0][d2]);
                a0 += qv.x * k0.x + qv.y * k0.y;
                if (j0 + 1 < BOARD) { float2 k1 = __half22float2(ks[j0+1][d2]); a1 += qv.x * k1.x + qv.y * k1.y; }
                if (j0 + 2 < BOARD) { float2 k2 = __half22float2(ks[j0+2][d2]); a2 += qv.x * k2.x + qv.y * k2.y; }
                if (j0 + 3 < BOARD) { float2 k3 = __half22float2(ks[j0+3][d2]); a3 += qv.x * k3.x + qv.y * k3.y; }
            }
            s[i][j0] = a0 * 0.125f;
            if (j0 + 1 < BOARD) s[i][j0+1] = a1 * 0.125f;
            if (j0 + 2 < BOARD) s[i][j0+2] = a2 * 0.125f;
            if (j0 + 3 < BOARD) s[i][j0+3] = a3 * 0.125f;
        }
    }
    __syncthreads();

    // softmax: warp w handles row w (w<8); rows 8,9 by warps 0,1 (second pass)
    {
        int warp = tid >> 5, lane = tid & 31;
        for (int pass = 0; pass < 2; pass++) {
            int row = warp + pass * 8;
            if (row < LL && (pass == 0 || warp < 2)) {
                float m0 = -1e30f;
                float v0 = (lane < BOARD)      ? s[row][lane]      : -1e30f;
                float v1 = (lane + 32 < BOARD) ? s[row][lane + 32] : -1e30f;
                float v2 = (lane + 64 < BOARD) ? s[row][lane + 64] : -1e30f;
                m0 = fmaxf(fmaxf(v0, v1), v2);
                #pragma unroll
                for (int o = 16; o; o >>= 1) m0 = fmaxf(m0, __shfl_xor_sync(0xffffffffu, m0, o));
                float e0 = (lane < BOARD)      ? expf(v0 - m0) : 0.f;
                float e1 = (lane + 32 < BOARD) ? expf(v1 - m0) : 0.f;
                float e2 = (lane + 64 < BOARD) ? expf(v2 - m0) : 0.f;
                float sm = e0 + e1 + e2;
                #pragma unroll
                for (int o = 16; o; o >>= 1) sm += __shfl_xor_sync(0xffffffffu, sm, o);
                float inv = 1.0f / sm;
                if (lane < BOARD)      s[row][lane]      = e0 * inv;
                if (lane + 32 < BOARD) s[row][lane + 32] = e1 * inv;
                if (lane + 64 < BOARD) s[row][lane + 64] = e2 * inv;
            }
        }
    }
    __syncthreads();

    // AV: thread handles (i2, d2) computing rows i2 and i2+5; V read once per pair
    {
        int idx = tid;                 // 5 * 32 = 160 work items
        if (idx < 160) {
            int i2 = idx >> 5, d2 = idx & 31;
            float ax0 = 0.f, ay0 = 0.f, ax1 = 0.f, ay1 = 0.f;
            #pragma unroll 2
            for (int j = 0; j < BOARD; j++) {
                float2 vv = __half22float2(vs[j][d2]);
                float s0 = s[i2][j], s1 = s[i2 + 5][j];
                ax0 += s0 * vv.x; ay0 += s0 * vv.y;
                ax1 += s1 * vv.x; ay1 += s1 * vv.y;
            }
            __half2* ob = (__half2*)O + ((size_t)b * LL) * 256 + h * 32 + d2;
            ob[(size_t)i2 * 256]       = __floats2half2_rn(ax0, ay0);
            ob[(size_t)(i2 + 5) * 256] = __floats2half2_rn(ax1, ay1);
        }
    }
}

// ---------------- host ----------------
static __half* s_wt;

static void tgemm(const __half* A, size_t woff, const float* bias, const float* res,
                  float* Cf, __half* Ch, int M, int N, int K, int Nc, int epi) {
    dim3 grid(N / 256, M / 128);
    tgemm_k<<<grid, 128, TG_SMEM>>>(A, s_wt + woff, bias, res, Cf, Ch, M, N, K, Nc, epi);
}

extern "C" void kernel_launch(void* const* d_in, const int* in_sizes, int n_in,
                              void* d_out, int out_size) {
    const int*   moves   = (const int*)d_in[0];
    const int*   lengths = (const int*)d_in[1];
    const float* boards  = (const float*)d_in[2];
    const float* emb     = (const float*)d_in[3];
    const float* pos     = (const float*)d_in[4];
    const float* sa_ln_g = (const float*)d_in[5];
    const float* sa_ln_b = (const float*)d_in[6];
    const float* sa_wq   = (const float*)d_in[7];
    const float* sa_bq   = (const float*)d_in[8];
    const float* sa_wkv  = (const float*)d_in[9];
    const float* sa_bkv  = (const float*)d_in[10];
    const float* sa_wo   = (const float*)d_in[11];
    const float* sa_bo   = (const float*)d_in[12];
    const float* ca_ln_g = (const float*)d_in[13];
    const float* ca_ln_b = (const float*)d_in[14];
    const float* ca_wq   = (const float*)d_in[15];
    const float* ca_bq   = (const float*)d_in[16];
    const float* ca_wkv  = (const float*)d_in[17];
    const float* ca_bkv  = (const float*)d_in[18];
    const float* ca_wo   = (const float*)d_in[19];
    const float* ca_bo   = (const float*)d_in[20];
    const float* ff_ln_g = (const float*)d_in[21];
    const float* ff_ln_b = (const float*)d_in[22];
    const float* ff_w1   = (const float*)d_in[23];
    const float* ff_b1   = (const float*)d_in[24];
    const float* ff_w2   = (const float*)d_in[25];
    const float* ff_b2   = (const float*)d_in[26];
    const float* fin_g   = (const float*)d_in[27];
    const float* fin_b   = (const float*)d_in[28];
    const float* fc_w    = (const float*)d_in[29];
    const float* fc_b    = (const float*)d_in[30];
    float* out = (float*)d_out;

    cudaFuncSetAttribute(tgemm_k, cudaFuncAttributeMaxDynamicSharedMemorySize, TG_SMEM);

    float *px, *pfcb, *pbqkv;
    __half *pxn, *pq, *pqkv, *pao, *ph, *pckv, *pbf;
    cudaGetSymbolAddress((void**)&px,    g_x);
    cudaGetSymbolAddress((void**)&pfcb,  g_fcb);
    cudaGetSymbolAddress((void**)&pbqkv, g_bqkv);
    cudaGetSymbolAddress((void**)&pxn,   g_xn);
    cudaGetSymbolAddress((void**)&pq,    g_q);
    cudaGetSymbolAddress((void**)&pqkv,  g_qkv);
    cudaGetSymbolAddress((void**)&pao,   g_ao);
    cudaGetSymbolAddress((void**)&ph,    g_h);
    cudaGetSymbolAddress((void**)&pckv,  g_ckv);
    cudaGetSymbolAddress((void**)&pbf,   g_bf);
    cudaGetSymbolAddress((void**)&s_wt,  g_wt);

    // prep: 3 launches; launch #4 = layer-0 caKV (the ncu target)
    wprep_k<<<(unsigned)((WTOT + 511) / 512), 512>>>(sa_wq, sa_wkv, sa_wo, ca_wq, ca_wkv,
                                                     ca_wo, ff_w1, ff_w2, fc_w);
    bconv_k<<<(unsigned)(((size_t)NBRD * DD) / 512), 512>>>(boards);
    misc_k<<<(NTOK * DD) / 512, 512>>>(fc_b, sa_bq, sa_bkv, moves, emb, pos);

    // layer-0 cross-KV (depends only on boards) hoisted
    tgemm(pbf, R_CAKV, ca_bkv, nullptr, nullptr, pckv, NBRD, 1024, 512, 1024, 3);

    for (int i = 0; i < NLAY; i++) {
        size_t WB = (size_t)i * PL;

        // ---- self attention ----
        ln_k<<<NTOK, 256>>>(px, sa_ln_g + i * DD, sa_ln_b + i * DD, pxn);
        tgemm(pxn, WB + R_SAQKV, pbqkv + i * 1536, nullptr, nullptr, pqkv,
              NTOK, 1536, 512, 1536, 3);
        selfattn_k<<<dim3(BB, HH), 128>>>(pqkv, lengths, pao);
        tgemm(pao, WB + R_SAO, sa_bo + i * DD, px, px, nullptr,
              NTOK, 512, 512, 512, 2);

        // ---- cross attention ----
        ln_k<<<NTOK, 256>>>(px, ca_ln_g + i * DD, ca_ln_b + i * DD, pxn);
        tgemm(pxn, WB + R_CAQ, ca_bq + i * 512, nullptr, nullptr, pq,
              NTOK, 512, 512, 512, 3);
        if (i > 0)
            tgemm(pbf, WB + R_CAKV, ca_bkv + i * 1024, nullptr, nullptr, pckv,
                  NBRD, 1024, 512, 1024, 3);
        crossattn_k<<<dim3(BB, HH), 256>>>(pq, pckv, pao);
        tgemm(pao, WB + R_CAO, ca_bo + i * DD, px, px, nullptr,
              NTOK, 512, 512, 512, 2);

        // ---- FFN ----
        ln_k<<<NTOK, 256>>>(px, ff_ln_g + i * DD, ff_ln_b + i * DD, pxn);
        tgemm(pxn, WB + R_FF1, ff_b1 + i * DI, nullptr, nullptr, ph,
              NTOK, DI, 512, DI, 1);
        tgemm(ph, WB + R_FF2, ff_b2 + i * DD, px, px, nullptr,
              NTOK, 512, DI, 512, 2);
    }

    ln_k<<<NTOK, 256>>>(px, fin_g, fin_b, pxn);
    tgemm(pxn, OFF_FC, pfcb, nullptr, out, nullptr, NTOK, VPAD, 512, VOCAB, 0);
}

// round 15
// speedup vs baseline: 2.5948x; 1.0103x over previous
#include <cuda_runtime.h>
#include <cuda_fp16.h>
#include <stdint.h>
#include <math.h>

#define BB 2048
#define LL 10
#define VOCAB 1974
#define DD 512
#define HH 8
#define DI 2048
#define NLAY 6
#define BOARD 70
#define NTOK (BB*LL)       /* 20480 */
#define NBRD (BB*BOARD)    /* 143360 */
#define VPAD 2048
#define CKVSZ 146800640ull /* NBRD*1024 */

#if defined(__CUDA_ARCH_FEAT_SM103_ALL) || defined(__CUDA_ARCH_FEAT_SM100_ALL) || defined(__CUDA_ARCH_FEAT_SM101_ALL)
#define TC5 1
#else
#define TC5 0
#endif

// ---- weight arena: per-layer blocks, [N,K] fp16 (g_wt) ----
#define PL       4194304ull
#define R_SAQKV  0ull
#define R_CAQ    786432ull
#define R_CAKV   1048576ull
#define R_SAO    1572864ull
#define R_CAO    1835008ull
#define R_FF1    2097152ull
#define R_FF2    3145728ull
#define OFF_FC   25165824ull
#define WTOT     26214400ull

// ---------------- scratch (static device buffers) ----------------
__device__ float  g_x   [NTOK*DD];
__device__ float  g_fcb [VPAD];
__device__ float  g_bqkv[NLAY*1536];
__device__ __half g_xn  [NTOK*DD];
__device__ __half g_q   [NTOK*DD];
__device__ __half g_qkv [NTOK*1536];
__device__ __half g_ao  [NTOK*DD];
__device__ __half g_h   [NTOK*DI];
__device__ __half g_ckv [NLAY*CKVSZ];     // per-layer cross-KV (1.76GB)
__device__ __half g_bf  [(size_t)NBRD*DD];
__device__ __half g_wt  [WTOT];    // [N,K]  (tcgen05)

// ---------------- prep: weights -> [N,K] fp16 (one launch, coalesced writes) ----------------
__global__ void wprep_k(const float* __restrict__ sawq, const float* __restrict__ sawkv,
                        const float* __restrict__ sawo, const float* __restrict__ cawq,
                        const float* __restrict__ cawkv, const float* __restrict__ cawo,
                        const float* __restrict__ ffw1, const float* __restrict__ ffw2,
                        const float* __restrict__ fcw) {
    size_t i = (size_t)blockIdx.x * blockDim.x + threadIdx.x;
    if (i >= WTOT) return;
    float v;
    if (i >= OFF_FC) {
        size_t r = i - OFF_FC;
        int n = (int)(r / 512), k = (int)(r % 512);
        v = (n < VOCAB) ? fcw[(size_t)k * VOCAB + n] : 0.f;
        g_wt[i] = __float2half_rn(v);
        return;
    }
    size_t l = i / PL, r = i % PL;
    int n, k;
    if (r < R_CAQ) {
        size_t r2 = r;
        n = (int)(r2 / 512); k = (int)(r2 % 512);
        v = (n < 512) ? sawq [l * 262144 + (size_t)k * 512  + n]
                      : sawkv[l * 524288 + (size_t)k * 1024 + (n - 512)];
    } else if (r < R_CAKV) {
        size_t r2 = r - R_CAQ;
        n = (int)(r2 / 512); k = (int)(r2 % 512);
        v = cawq[l * 262144 + (size_t)k * 512 + n];
    } else if (r < R_SAO) {
        size_t r2 = r - R_CAKV;
        n = (int)(r2 / 512); k = (int)(r2 % 512);
        v = cawkv[l * 524288 + (size_t)k * 1024 + n];
    } else if (r < R_CAO) {
        size_t r2 = r - R_SAO;
        n = (int)(r2 / 512); k = (int)(r2 % 512);
        v = sawo[l * 262144 + (size_t)k * 512 + n];
    } else if (r < R_FF1) {
        size_t r2 = r - R_CAO;
        n = (int)(r2 / 512); k = (int)(r2 % 512);
        v = cawo[l * 262144 + (size_t)k * 512 + n];
    } else if (r < R_FF2) {
        size_t r2 = r - R_FF1;
        n = (int)(r2 / 512); k = (int)(r2 % 512);
        v = ffw1[l * 1048576 + (size_t)k * 2048 + n];
    } else {
        size_t r2 = r - R_FF2;
        n = (int)(r2 / 2048); k = (int)(r2 % 2048);
        v = ffw2[l * 1048576 + (size_t)k * 512 + n];
    }
    g_wt[i] = __float2half_rn(v);
}

__global__ void bconv_k(const float* __restrict__ boards) {
    size_t i = (size_t)blockIdx.x * blockDim.x + threadIdx.x;
    g_bf[i] = __float2half_rn(boards[i]);
}

// fcb copy + qkv-bias concat + embedding, one launch
__global__ void misc_k(const float* __restrict__ fcb,
                       const float* __restrict__ sa_bq, const float* __restrict__ sa_bkv,
                       const int* __restrict__ moves,
                       const float* __restrict__ emb, const float* __restrict__ pos) {
    size_t i = (size_t)blockIdx.x * blockDim.x + threadIdx.x;
    if (i < VPAD) g_fcb[i] = (i < VOCAB) ? fcb[i] : 0.f;
    if (i < NLAY * 1536) {
        int l = (int)(i / 1536), j = (int)(i % 1536);
        g_bqkv[i] = (j < 512) ? sa_bq[l * 512 + j] : sa_bkv[l * 1024 + (j - 512)];
    }
    if (i < (size_t)NTOK * DD) {
        int tok = (int)(i / DD), d = (int)(i % DD);
        g_x[i] = emb[(size_t)moves[tok] * DD + d] * 22.62741699796952f
               + pos[(size_t)(tok % LL) * DD + d];
    }
}

// ---------------- layernorm -> fp16 ----------------
__global__ __launch_bounds__(256) void ln_k(const float* __restrict__ X,
                                            const float* __restrict__ g,
                                            const float* __restrict__ b,
                                            __half* __restrict__ Y) {
    int row = blockIdx.x;
    const float2* x2 = (const float2*)(X + (size_t)row * DD);
    float2 v = x2[threadIdx.x];
    float s  = v.x + v.y;
    float ss = v.x * v.x + v.y * v.y;
    #pragma unroll
    for (int o = 16; o; o >>= 1) {
        s  += __shfl_down_sync(0xffffffffu, s,  o);
        ss += __shfl_down_sync(0xffffffffu, ss, o);
    }
    __shared__ float rs[8], rss[8];
    int w = threadIdx.x >> 5;
    if ((threadIdx.x & 31) == 0) { rs[w] = s; rss[w] = ss; }
    __syncthreads();
    if (threadIdx.x == 0) {
        float a = 0.f, c = 0.f;
        #pragma unroll
        for (int i = 0; i < 8; i++) { a += rs[i]; c += rss[i]; }
        rs[0] = a; rss[0] = c;
    }
    __syncthreads();
    float mean = rs[0] * (1.0f / DD);
    float var  = rss[0] * (1.0f / DD) - mean * mean;
    float rstd = rsqrtf(var + 1e-5f);
    float2 gg = ((const float2*)g)[threadIdx.x];
    float2 bb = ((const float2*)b)[threadIdx.x];
    size_t base = (size_t)row * DD + threadIdx.x * 2;
    Y[base]     = __float2half_rn((v.x - mean) * rstd * gg.x + bb.x);
    Y[base + 1] = __float2half_rn((v.y - mean) * rstd * gg.y + bb.y);
}

#if TC5
__device__ __forceinline__ uint32_t elect1() {
    uint32_t p;
    asm volatile("{\n\t.reg .pred p;\n\telect.sync _|p, 0xFFFFFFFF;\n\tselp.b32 %0, 1, 0, p;\n\t}"
                 : "=r"(p));
    return p;
}
#endif

#define MB_WAIT(mbar, ph) do {                                                        \
    uint32_t _d;                                                                      \
    do {                                                                              \
        asm volatile("{\n\t.reg .pred p;\n\t"                                         \
            "mbarrier.try_wait.parity.acquire.cta.shared::cta.b64 p, [%1], %2, 0x989680;\n\t" \
            "selp.b32 %0, 1, 0, p;\n\t}"                                              \
            : "=r"(_d) : "r"(mbar), "r"((uint32_t)(ph)) : "memory");                  \
    } while (!_d);                                                                    \
} while (0)

// SW128 K-major descriptor base: layout=SW128(2), version=1, SBO=64, LBO=1
#define DESC_BASE ((2ull<<61)|(1ull<<46)|(64ull<<32)|(1ull<<16))
// idesc kind::f16: dtype=F32, atype=btype=F16(0), N=256, M=128
#define IDESC_F16 ((1u<<4) | (32u<<17) | (8u<<24))

#define STAGE_SZ 49152                 /* A 16KB + B 32KB */
#define TG_SMEM  (1024 + 2*STAGE_SZ)   /* 99328; 2 CTAs/SM */

// ---------------- GEMM: C[M,Nc] = A[M,K] @ Wt^T, 128x256 tiles, 2-stage ----------------
// epi: 0 +bias->f32  1 relu(+bias)->f16  2 +bias+res->f32  3 +bias->f16
__global__ __launch_bounds__(128, 2) void tgemm_k(
    const __half* __restrict__ A, const __half* __restrict__ Wt,
    const float* __restrict__ bias, const float* __restrict__ res,
    float* __restrict__ Cf, __half* __restrict__ Ch,
    int M, int N, int K, int Nc, int epi)
{
    extern __shared__ __align__(16) char smem[];
    const int tid  = threadIdx.x;
    const int lane = tid & 31;
    const int warp = tid >> 5;
    const int m0 = blockIdx.y * 128, n0 = blockIdx.x * 256;

#if TC5
    const uint32_t sb  = (uint32_t)__cvta_generic_to_shared(smem);
    const uint32_t MB0 = sb + 16;          // two mma-done barriers
    const uint32_t SMT = sb + 1024;
    const int KT = K >> 6;

    if (warp == 0) {
        asm volatile("tcgen05.alloc.cta_group::1.sync.aligned.shared::cta.b32 [%0], 256;"
                     :: "r"(sb) : "memory");
        asm volatile("tcgen05.relinquish_alloc_permit.cta_group::1.sync.aligned;");
    }
    if (tid == 0) {
        asm volatile("mbarrier.init.shared.b64 [%0], 1;" :: "r"(MB0)     : "memory");
        asm volatile("mbarrier.init.shared.b64 [%0], 1;" :: "r"(MB0 + 8) : "memory");
    }
    __syncthreads();
    uint32_t tmem;
    asm volatile("ld.shared.b32 %0, [%1];" : "=r"(tmem) : "r"(sb));

    const __half* Ab = A  + (size_t)m0 * K;
    const __half* Bb = Wt + (size_t)n0 * K;
    const uint32_t goB2 = (uint32_t)(K << 7);   // +128 rows (halves)

    uint32_t swo[8], go[8];
    #pragma unroll
    for (int i = 0; i < 8; i++) {
        int c = tid + i * 128;
        int row = c >> 3, cb = (c & 7) << 4;
        int bo = (row << 7) + cb;
        swo[i] = (uint32_t)(bo ^ ((bo >> 3) & 0x70));
        go[i]  = (uint32_t)(row * K + (cb >> 1));
    }

    #define LOADT(kt, s) do {                                                         \
        const __half* aP = Ab + (kt) * 64;                                            \
        const __half* bP = Bb + (kt) * 64;                                            \
        uint32_t baA = SMT + (s) * STAGE_SZ, baB = baA + 16384;                       \
        _Pragma("unroll")                                                             \
        for (int i = 0; i < 8; i++) {                                                 \
            asm volatile("cp.async.cg.shared.global [%0], [%1], 16;"                  \
                :: "r"(baA + swo[i]), "l"((const void*)(aP + go[i])) : "memory");     \
            asm volatile("cp.async.cg.shared.global [%0], [%1], 16;"                  \
                :: "r"(baB + swo[i]), "l"((const void*)(bP + go[i])) : "memory");     \
            asm volatile("cp.async.cg.shared.global [%0], [%1], 16;"                  \
                :: "r"(baB + 16384 + swo[i]), "l"((const void*)(bP + goB2 + go[i])) : "memory"); \
        }                                                                             \
        asm volatile("cp.async.commit_group;" ::: "memory");                          \
    } while (0)

    LOADT(0, 0);
    if (KT > 1) LOADT(1, 1);

    for (int kt = 0; kt < KT; kt++) {
        if (kt + 1 < KT) asm volatile("cp.async.wait_group 1;" ::: "memory");
        else             asm volatile("cp.async.wait_group 0;" ::: "memory");
        asm volatile("fence.proxy.async.shared::cta;" ::: "memory");
        __syncthreads();
        if (warp == 0 && elect1()) {
            uint32_t base = SMT + (kt & 1) * STAGE_SZ;
            uint64_t ad = DESC_BASE | (uint64_t)((base >> 4) & 0x3FFF);
            uint64_t bd = DESC_BASE | (uint64_t)(((base + 16384) >> 4) & 0x3FFF);
            #pragma unroll
            for (int s = 0; s < 4; s++) {
                uint32_t en = (kt > 0 || s > 0) ? 1u : 0u;
                asm volatile(
                    "{\n\t.reg .pred p;\n\tsetp.ne.u32 p, %5, 0;\n\t"
                    "tcgen05.mma.cta_group::1.kind::f16 [%0], %1, %2, %3, {%4,%4,%4,%4}, p;\n\t}"
                    :: "r"(tmem), "l"(ad + s * 2), "l"(bd + s * 2),
                       "r"(IDESC_F16), "r"(0u), "r"(en) : "memory");
            }
            asm volatile(
                "tcgen05.commit.cta_group::1.mbarrier::arrive::one.shared::cluster.b64 [%0];"
                :: "r"(MB0 + (uint32_t)(kt & 1) * 8) : "memory");
        }
        if (kt + 2 < KT) {
            MB_WAIT(MB0 + (uint32_t)(kt & 1) * 8, (uint32_t)((kt >> 1) & 1));
            LOADT(kt + 2, kt & 1);
        }
    }
    {
        int j = KT - 1;
        MB_WAIT(MB0 + (uint32_t)(j & 1) * 8, (uint32_t)((j >> 1) & 1));
    }
    asm volatile("tcgen05.fence::after_thread_sync;" ::: "memory");
    __syncthreads();

    // ---- epilogue: 64-col chunks staged in smem, vectorized coalesced stores ----
    float* osm = (float*)(smem + 1024);          // [128][66]
    for (int cb = 0; cb < 256; cb += 64) {
        uint32_t d0[32], d1[32];
        asm volatile(
            "tcgen05.ld.sync.aligned.32x32b.x32.b32 "
            "{%0,%1,%2,%3,%4,%5,%6,%7,%8,%9,%10,%11,%12,%13,%14,%15,"
            "%16,%17,%18,%19,%20,%21,%22,%23,%24,%25,%26,%27,%28,%29,%30,%31}, [%32];"
            : "=r"(d0[0]),"=r"(d0[1]),"=r"(d0[2]),"=r"(d0[3]),"=r"(d0[4]),"=r"(d0[5]),
              "=r"(d0[6]),"=r"(d0[7]),"=r"(d0[8]),"=r"(d0[9]),"=r"(d0[10]),"=r"(d0[11]),
              "=r"(d0[12]),"=r"(d0[13]),"=r"(d0[14]),"=r"(d0[15]),"=r"(d0[16]),"=r"(d0[17]),
              "=r"(d0[18]),"=r"(d0[19]),"=r"(d0[20]),"=r"(d0[21]),"=r"(d0[22]),"=r"(d0[23]),
              "=r"(d0[24]),"=r"(d0[25]),"=r"(d0[26]),"=r"(d0[27]),"=r"(d0[28]),"=r"(d0[29]),
              "=r"(d0[30]),"=r"(d0[31])
            : "r"(tmem + cb));
        asm volatile(
            "tcgen05.ld.sync.aligned.32x32b.x32.b32 "
            "{%0,%1,%2,%3,%4,%5,%6,%7,%8,%9,%10,%11,%12,%13,%14,%15,"
            "%16,%17,%18,%19,%20,%21,%22,%23,%24,%25,%26,%27,%28,%29,%30,%31}, [%32];"
            : "=r"(d1[0]),"=r"(d1[1]),"=r"(d1[2]),"=r"(d1[3]),"=r"(d1[4]),"=r"(d1[5]),
              "=r"(d1[6]),"=r"(d1[7]),"=r"(d1[8]),"=r"(d1[9]),"=r"(d1[10]),"=r"(d1[11]),
              "=r"(d1[12]),"=r"(d1[13]),"=r"(d1[14]),"=r"(d1[15]),"=r"(d1[16]),"=r"(d1[17]),
              "=r"(d1[18]),"=r"(d1[19]),"=r"(d1[20]),"=r"(d1[21]),"=r"(d1[22]),"=r"(d1[23]),
              "=r"(d1[24]),"=r"(d1[25]),"=r"(d1[26]),"=r"(d1[27]),"=r"(d1[28]),"=r"(d1[29]),
              "=r"(d1[30]),"=r"(d1[31])
            : "r"(tmem + cb + 32));
        asm volatile("tcgen05.wait::ld.sync.aligned;" ::: "memory");
        float* rowp = osm + tid * 66;
        #pragma unroll
        for (int c = 0; c < 32; c++) { rowp[c] = __uint_as_float(d0[c]); rowp[32 + c] = __uint_as_float(d1[c]); }
        __syncthreads();
        const int colb = n0 + cb;
        const int c2 = lane * 2;
        if (colb + 64 <= Nc) {
            float b0 = bias[colb + c2], b1 = bias[colb + c2 + 1];
            for (int rr = warp; rr < 128; rr += 4) {
                float v0 = osm[rr * 66 + c2] + b0;
                float v1 = osm[rr * 66 + c2 + 1] + b1;
                size_t off = (size_t)(m0 + rr) * Nc + colb + c2;
                if (epi == 2) {
                    float2 rv = *(const float2*)(res + off);
                    *(float2*)(Cf + off) = make_float2(v0 + rv.x, v1 + rv.y);
                } else if (epi == 0) {
                    *(float2*)(Cf + off) = make_float2(v0, v1);
                } else {
                    if (epi == 1) { v0 = fmaxf(v0, 0.f); v1 = fmaxf(v1, 0.f); }
                    *(__half2*)(Ch + off) = __floats2half2_rn(v0, v1);
                }
            }
        } else {
            for (int rr = warp; rr < 128; rr += 4) {
                #pragma unroll
                for (int q = 0; q < 2; q++) {
                    int c = colb + c2 + q;
                    if (c < Nc) {
                        float v = osm[rr * 66 + c2 + q] + bias[c];
                        size_t off = (size_t)(m0 + rr) * Nc + c;
                        if (epi == 2)      Cf[off] = v + res[off];
                        else if (epi == 0) Cf[off] = v;
                        else if (epi == 1) Ch[off] = __float2half_rn(fmaxf(v, 0.f));
                        else               Ch[off] = __float2half_rn(v);
                    }
                }
            }
        }
        __syncthreads();
    }

    if (tid == 0) {
        asm volatile("mbarrier.inval.shared.b64 [%0];" :: "r"(MB0)     : "memory");
        asm volatile("mbarrier.inval.shared.b64 [%0];" :: "r"(MB0 + 8) : "memory");
    }
    __syncthreads();
    if (warp == 0)
        asm volatile("tcgen05.dealloc.cta_group::1.sync.aligned.b32 %0, 256;" :: "r"(tmem));
    #undef LOADT

#else
    // ===== naive fallback (never executed on sm_103a; kept for non-'a' pass validity) =====
    for (int idx = tid; idx < 128 * 256; idx += 128) {
        int m = m0 + idx / 256;
        int n = n0 + (idx % 256);
        if (m < M && n < Nc) {
            float acc = bias[n];
            const __half* ap = A + (size_t)m * K;
            const __half* wp = Wt + (size_t)n * K;
            for (int k = 0; k < K; k++) acc += __half2float(ap[k]) * __half2float(wp[k]);
            size_t off = (size_t)m * Nc + n;
            if (epi == 0)      Cf[off] = acc;
            else if (epi == 1) Ch[off] = __float2half_rn(fmaxf(acc, 0.f));
            else if (epi == 2) Cf[off] = acc + res[off];
            else               Ch[off] = __float2half_rn(acc);
        }
    }
#endif
}

// ---------------- self attention v2: per (b,h), half2 smem, 128 threads ----------------
__global__ __launch_bounds__(128) void selfattn_k(const __half* __restrict__ QKV,
                                                  const int* __restrict__ lengths,
                                                  __half* __restrict__ O) {
    int b = blockIdx.x, h = blockIdx.y;
    __shared__ __half2 qs[LL][33], ks[LL][33], vs[LL][33];
    __shared__ float s[LL][12];
    int tid = threadIdx.x;
    int len = lengths[b];
    const __half2* base = (const __half2*)QKV + ((size_t)b * LL) * 768 + h * 32;
    for (int idx = tid; idx < LL * 32; idx += 128) {
        int i = idx >> 5, d2 = idx & 31;
        const __half2* rp = base + (size_t)i * 768 + d2;
        qs[i][d2] = rp[0];
        ks[i][d2] = rp[256];
        vs[i][d2] = rp[512];
    }
    __syncthreads();
    for (int idx = tid; idx < LL * LL; idx += 128) {
        int i = idx / LL, j = idx % LL;
        float acc = 0.f;
        if (j <= i && j < len) {
            #pragma unroll
            for (int d2 = 0; d2 < 32; d2++) {
                float2 qv = __half22float2(qs[i][d2]);
                float2 kv = __half22float2(ks[j][d2]);
                acc += qv.x * kv.x + qv.y * kv.y;
            }
            acc *= 0.125f;
        } else acc = -1e30f;
        s[i][j] = acc;
    }
    __syncthreads();
    if (tid < LL) {
        float mx = -1e30f;
        #pragma unroll
        for (int j = 0; j < LL; j++) mx = fmaxf(mx, s[tid][j]);
        float sum = 0.f;
        #pragma unroll
        for (int j = 0; j < LL; j++) { float e = expf(s[tid][j] - mx); s[tid][j] = e; sum += e; }
        float inv = 1.0f / sum;
        #pragma unroll
        for (int j = 0; j < LL; j++) s[tid][j] *= inv;
    }
    __syncthreads();
    __half2* ob = (__half2*)O + ((size_t)b * LL) * 256 + h * 32;
    for (int idx = tid; idx < LL * 32; idx += 128) {
        int i = idx >> 5, d2 = idx & 31;
        float ax = 0.f, ay = 0.f;
        #pragma unroll
        for (int j = 0; j < LL; j++) {
            float sv = s[i][j];
            float2 vv = __half22float2(vs[j][d2]);
            ax += sv * vv.x; ay += sv * vv.y;
        }
        ob[(size_t)i * 256 + d2] = __floats2half2_rn(ax, ay);
    }
}

// ---------------- cross attention v2: per (b,h), half2 smem, 256 threads ----------------
__global__ __launch_bounds__(256) void crossattn_k(const __half* __restrict__ Q,
                                                   const __half* __restrict__ CKV,
                                                   __half* __restrict__ O) {
    int b = blockIdx.x, h = blockIdx.y;
    __shared__ __half2 qs[LL][33];
    __shared__ __half2 ks[BOARD][33], vs[BOARD][33];
    __shared__ float s[LL][72];
    int tid = threadIdx.x;

    const __half2* qb = (const __half2*)Q + ((size_t)b * LL) * 256 + h * 32;
    for (int idx = tid; idx < LL * 32; idx += 256) {
        int i = idx >> 5, d2 = idx & 31;
        qs[i][d2] = qb[(size_t)i * 256 + d2];
    }
    const __half2* cb = (const __half2*)CKV + ((size_t)b * BOARD) * 512 + h * 32;
    for (int idx = tid; idx < BOARD * 32; idx += 256) {
        int j = idx >> 5, d2 = idx & 31;
        const __half2* rp = cb + (size_t)j * 512 + d2;
        ks[j][d2] = rp[0];
        vs[j][d2] = rp[256];
    }
    __syncthreads();

    // scores: thread handles (i, 4 consecutive j)
    {
        int idx = tid;                 // 10 * 18 = 180 work items
        if (idx < 180) {
            int i = idx / 18, g = idx % 18;
            int j0 = g * 4;
            float a0 = 0.f, a1 = 0.f, a2 = 0.f, a3 = 0.f;
            #pragma unroll
            for (int d2 = 0; d2 < 32; d2++) {
                float2 qv = __half22float2(qs[i][d2]);
                float2 k0 = __half22float2(ks[j0][d2]);
                a0 += qv.x * k0.x + qv.y * k0.y;
                if (j0 + 1 < BOARD) { float2 k1 = __half22float2(ks[j0+1][d2]); a1 += qv.x * k1.x + qv.y * k1.y; }
                if (j0 + 2 < BOARD) { float2 k2 = __half22float2(ks[j0+2][d2]); a2 += qv.x * k2.x + qv.y * k2.y; }
                if (j0 + 3 < BOARD) { float2 k3 = __half22float2(ks[j0+3][d2]); a3 += qv.x * k3.x + qv.y * k3.y; }
            }
            s[i][j0] = a0 * 0.125f;
            if (j0 + 1 < BOARD) s[i][j0+1] = a1 * 0.125f;
            if (j0 + 2 < BOARD) s[i][j0+2] = a2 * 0.125f;
            if (j0 + 3 < BOARD) s[i][j0+3] = a3 * 0.125f;
        }
    }
    __syncthreads();

    // softmax: warp w handles row w (w<8); rows 8,9 by warps 0,1 (second pass)
    {
        int warp = tid >> 5, lane = tid & 31;
        for (int pass = 0; pass < 2; pass++) {
            int row = warp + pass * 8;
            if (row < LL && (pass == 0 || warp < 2)) {
                float m0 = -1e30f;
                float v0 = (lane < BOARD)      ? s[row][lane]      : -1e30f;
                float v1 = (lane + 32 < BOARD) ? s[row][lane + 32] : -1e30f;
                float v2 = (lane + 64 < BOARD) ? s[row][lane + 64] : -1e30f;
                m0 = fmaxf(fmaxf(v0, v1), v2);
                #pragma unroll
                for (int o = 16; o; o >>= 1) m0 = fmaxf(m0, __shfl_xor_sync(0xffffffffu, m0, o));
                float e0 = (lane < BOARD)      ? expf(v0 - m0) : 0.f;
                float e1 = (lane + 32 < BOARD) ? expf(v1 - m0) : 0.f;
                float e2 = (lane + 64 < BOARD) ? expf(v2 - m0) : 0.f;
                float sm = e0 + e1 + e2;
                #pragma unroll
                for (int o = 16; o; o >>= 1) sm += __shfl_xor_sync(0xffffffffu, sm, o);
                float inv = 1.0f / sm;
                if (lane < BOARD)      s[row][lane]      = e0 * inv;
                if (lane + 32 < BOARD) s[row][lane + 32] = e1 * inv;
                if (lane + 64 < BOARD) s[row][lane + 64] = e2 * inv;
            }
        }
    }
    __syncthreads();

    // AV: thread handles (i2, d2) computing rows i2 and i2+5; V read once per pair
    {
        int idx = tid;                 // 5 * 32 = 160 work items
        if (idx < 160) {
            int i2 = idx >> 5, d2 = idx & 31;
            float ax0 = 0.f, ay0 = 0.f, ax1 = 0.f, ay1 = 0.f;
            #pragma unroll 2
            for (int j = 0; j < BOARD; j++) {
                float2 vv = __half22float2(vs[j][d2]);
                float s0 = s[i2][j], s1 = s[i2 + 5][j];
                ax0 += s0 * vv.x; ay0 += s0 * vv.y;
                ax1 += s1 * vv.x; ay1 += s1 * vv.y;
            }
            __half2* ob = (__half2*)O + ((size_t)b * LL) * 256 + h * 32 + d2;
            ob[(size_t)i2 * 256]       = __floats2half2_rn(ax0, ay0);
            ob[(size_t)(i2 + 5) * 256] = __floats2half2_rn(ax1, ay1);
        }
    }
}

// ---------------- host ----------------
static __half* s_wt;

static void tgemm_s(cudaStream_t st, const __half* A, size_t woff, const float* bias,
                    const float* res, float* Cf, __half* Ch,
                    int M, int N, int K, int Nc, int epi) {
    dim3 grid(N / 256, M / 128);
    tgemm_k<<<grid, 128, TG_SMEM, st>>>(A, s_wt + woff, bias, res, Cf, Ch, M, N, K, Nc, epi);
}

extern "C" void kernel_launch(void* const* d_in, const int* in_sizes, int n_in,
                              void* d_out, int out_size) {
    const int*   moves   = (const int*)d_in[0];
    const int*   lengths = (const int*)d_in[1];
    const float* boards  = (const float*)d_in[2];
    const float* emb     = (const float*)d_in[3];
    const float* pos     = (const float*)d_in[4];
    const float* sa_ln_g = (const float*)d_in[5];
    const float* sa_ln_b = (const float*)d_in[6];
    const float* sa_wq   = (const float*)d_in[7];
    const float* sa_bq   = (const float*)d_in[8];
    const float* sa_wkv  = (const float*)d_in[9];
    const float* sa_bkv  = (const float*)d_in[10];
    const float* sa_wo   = (const float*)d_in[11];
    const float* sa_bo   = (const float*)d_in[12];
    const float* ca_ln_g = (const float*)d_in[13];
    const float* ca_ln_b = (const float*)d_in[14];
    const float* ca_wq   = (const float*)d_in[15];
    const float* ca_bq   = (const float*)d_in[16];
    const float* ca_wkv  = (const float*)d_in[17];
    const float* ca_bkv  = (const float*)d_in[18];
    const float* ca_wo   = (const float*)d_in[19];
    const float* ca_bo   = (const float*)d_in[20];
    const float* ff_ln_g = (const float*)d_in[21];
    const float* ff_ln_b = (const float*)d_in[22];
    const float* ff_w1   = (const float*)d_in[23];
    const float* ff_b1   = (const float*)d_in[24];
    const float* ff_w2   = (const float*)d_in[25];
    const float* ff_b2   = (const float*)d_in[26];
    const float* fin_g   = (const float*)d_in[27];
    const float* fin_b   = (const float*)d_in[28];
    const float* fc_w    = (const float*)d_in[29];
    const float* fc_b    = (const float*)d_in[30];
    float* out = (float*)d_out;

    // one-time infra (created on the uncaptured correctness call)
    static cudaStream_t s2 = nullptr;
    static cudaEvent_t evB = nullptr;
    static cudaEvent_t evK[NLAY];
    if (!s2) {
        cudaStreamCreateWithFlags(&s2, cudaStreamNonBlocking);
        cudaEventCreateWithFlags(&evB, cudaEventDisableTiming);
        for (int i = 0; i < NLAY; i++)
            cudaEventCreateWithFlags(&evK[i], cudaEventDisableTiming);
        cudaFuncSetAttribute(tgemm_k, cudaFuncAttributeMaxDynamicSharedMemorySize, TG_SMEM);
    }

    float *px, *pfcb, *pbqkv;
    __half *pxn, *pq, *pqkv, *pao, *ph, *pckv, *pbf;
    cudaGetSymbolAddress((void**)&px,    g_x);
    cudaGetSymbolAddress((void**)&pfcb,  g_fcb);
    cudaGetSymbolAddress((void**)&pbqkv, g_bqkv);
    cudaGetSymbolAddress((void**)&pxn,   g_xn);
    cudaGetSymbolAddress((void**)&pq,    g_q);
    cudaGetSymbolAddress((void**)&pqkv,  g_qkv);
    cudaGetSymbolAddress((void**)&pao,   g_ao);
    cudaGetSymbolAddress((void**)&ph,    g_h);
    cudaGetSymbolAddress((void**)&pckv,  g_ckv);
    cudaGetSymbolAddress((void**)&pbf,   g_bf);
    cudaGetSymbolAddress((void**)&s_wt,  g_wt);

    // prep on main stream
    wprep_k<<<(unsigned)((WTOT + 511) / 512), 512>>>(sa_wq, sa_wkv, sa_wo, ca_wq, ca_wkv,
                                                     ca_wo, ff_w1, ff_w2, fc_w);
    bconv_k<<<(unsigned)(((size_t)NBRD * DD) / 512), 512>>>(boards);
    cudaEventRecord(evB, 0);
    misc_k<<<(NTOK * DD) / 512, 512>>>(fc_b, sa_bq, sa_bkv, moves, emb, pos);

    // side stream: all six cross-KV GEMMs (depend only on boards + weights)
    cudaStreamWaitEvent(s2, evB, 0);
    for (int i = 0; i < NLAY; i++) {
        tgemm_s(s2, pbf, (size_t)i * PL + R_CAKV, ca_bkv + i * 1024, nullptr,
                nullptr, pckv + (size_t)i * CKVSZ, NBRD, 1024, 512, 1024, 3);
        cudaEventRecord(evK[i], s2);
    }

    for (int i = 0; i < NLAY; i++) {
        size_t WB = (size_t)i * PL;

        // ---- self attention ----
        ln_k<<<NTOK, 256>>>(px, sa_ln_g + i * DD, sa_ln_b + i * DD, pxn);
        tgemm_s(0, pxn, WB + R_SAQKV, pbqkv + i * 1536, nullptr, nullptr, pqkv,
                NTOK, 1536, 512, 1536, 3);
        selfattn_k<<<dim3(BB, HH), 128>>>(pqkv, lengths, pao);
        tgemm_s(0, pao, WB + R_SAO, sa_bo + i * DD, px, px, nullptr,
                NTOK, 512, 512, 512, 2);

        // ---- cross attention ----
        ln_k<<<NTOK, 256>>>(px, ca_ln_g + i * DD, ca_ln_b + i * DD, pxn);
        tgemm_s(0, pxn, WB + R_CAQ, ca_bq + i * 512, nullptr, nullptr, pq,
                NTOK, 512, 512, 512, 3);
        cudaStreamWaitEvent(0, evK[i], 0);
        crossattn_k<<<dim3(BB, HH), 256>>>(pq, pckv + (size_t)i * CKVSZ, pao);
        tgemm_s(0, pao, WB + R_CAO, ca_bo + i * DD, px, px, nullptr,
                NTOK, 512, 512, 512, 2);

        // ---- FFN ----
        ln_k<<<NTOK, 256>>>(px, ff_ln_g + i * DD, ff_ln_b + i * DD, pxn);
        tgemm_s(0, pxn, WB + R_FF1, ff_b1 + i * DI, nullptr, nullptr, ph,
                NTOK, DI, 512, DI, 1);
        tgemm_s(0, ph, WB + R_FF2, ff_b2 + i * DD, px, px, nullptr,
                NTOK, 512, DI, 512, 2);
    }

    ln_k<<<NTOK, 256>>>(px, fin_g, fin_b, pxn);
    tgemm_s(0, pxn, OFF_FC, pfcb, nullptr, out, nullptr, NTOK, VPAD, 512, VOCAB, 0);
}

// round 17
// speedup vs baseline: 2.6327x; 1.0146x over previous
#include <cuda_runtime.h>
#include <cuda_fp16.h>
#include <stdint.h>
#include <math.h>

#define BB 2048
#define LL 10
#define VOCAB 1974
#define DD 512
#define HH 8
#define DI 2048
#define NLAY 6
#define BOARD 70
#define NTOK (BB*LL)       /* 20480 */
#define NBRD (BB*BOARD)    /* 143360 */
#define VPAD 2048
#define CKVSZ 146800640ull /* NBRD*1024 */

#if defined(__CUDA_ARCH_FEAT_SM103_ALL) || defined(__CUDA_ARCH_FEAT_SM100_ALL) || defined(__CUDA_ARCH_FEAT_SM101_ALL)
#define TC5 1
#else
#define TC5 0
#endif

// ---- weight arena: per-layer blocks, [N,K] fp16 (g_wt) ----
#define PL       4194304ull
#define R_SAQKV  0ull
#define R_CAQ    786432ull
#define R_CAKV   1048576ull
#define R_SAO    1572864ull
#define R_CAO    1835008ull
#define R_FF1    2097152ull
#define R_FF2    3145728ull
#define OFF_FC   25165824ull
#define WTOT     26214400ull

// ---------------- scratch (static device buffers) ----------------
__device__ float  g_x   [NTOK*DD];
__device__ float  g_fcb [VPAD];
__device__ float  g_bqkv[NLAY*1536];
__device__ __half g_xn  [NTOK*DD];
__device__ __half g_q   [NTOK*DD];
__device__ __half g_qkv [NTOK*1536];
__device__ __half g_ao  [NTOK*DD];
__device__ __half g_h   [NTOK*DI];
__device__ __half g_ckv [NLAY*CKVSZ];     // per-layer cross-KV (1.76GB)
__device__ __half g_bf  [(size_t)NBRD*DD];
__device__ __half g_wt  [WTOT];    // [N,K]  (tcgen05)

// ---------------- prep: weights -> [N,K] fp16 (one launch, coalesced writes) ----------------
__global__ void wprep_k(const float* __restrict__ sawq, const float* __restrict__ sawkv,
                        const float* __restrict__ sawo, const float* __restrict__ cawq,
                        const float* __restrict__ cawkv, const float* __restrict__ cawo,
                        const float* __restrict__ ffw1, const float* __restrict__ ffw2,
                        const float* __restrict__ fcw) {
    size_t i = (size_t)blockIdx.x * blockDim.x + threadIdx.x;
    if (i >= WTOT) return;
    float v;
    if (i >= OFF_FC) {
        size_t r = i - OFF_FC;
        int n = (int)(r / 512), k = (int)(r % 512);
        v = (n < VOCAB) ? fcw[(size_t)k * VOCAB + n] : 0.f;
        g_wt[i] = __float2half_rn(v);
        return;
    }
    size_t l = i / PL, r = i % PL;
    int n, k;
    if (r < R_CAQ) {
        size_t r2 = r;
        n = (int)(r2 / 512); k = (int)(r2 % 512);
        v = (n < 512) ? sawq [l * 262144 + (size_t)k * 512  + n]
                      : sawkv[l * 524288 + (size_t)k * 1024 + (n - 512)];
    } else if (r < R_CAKV) {
        size_t r2 = r - R_CAQ;
        n = (int)(r2 / 512); k = (int)(r2 % 512);
        v = cawq[l * 262144 + (size_t)k * 512 + n];
    } else if (r < R_SAO) {
        size_t r2 = r - R_CAKV;
        n = (int)(r2 / 512); k = (int)(r2 % 512);
        v = cawkv[l * 524288 + (size_t)k * 1024 + n];
    } else if (r < R_CAO) {
        size_t r2 = r - R_SAO;
        n = (int)(r2 / 512); k = (int)(r2 % 512);
        v = sawo[l * 262144 + (size_t)k * 512 + n];
    } else if (r < R_FF1) {
        size_t r2 = r - R_CAO;
        n = (int)(r2 / 512); k = (int)(r2 % 512);
        v = cawo[l * 262144 + (size_t)k * 512 + n];
    } else if (r < R_FF2) {
        size_t r2 = r - R_FF1;
        n = (int)(r2 / 512); k = (int)(r2 % 512);
        v = ffw1[l * 1048576 + (size_t)k * 2048 + n];
    } else {
        size_t r2 = r - R_FF2;
        n = (int)(r2 / 2048); k = (int)(r2 % 2048);
        v = ffw2[l * 1048576 + (size_t)k * 512 + n];
    }
    g_wt[i] = __float2half_rn(v);
}

__global__ void bconv_k(const float* __restrict__ boards) {
    size_t i = (size_t)blockIdx.x * blockDim.x + threadIdx.x;
    g_bf[i] = __float2half_rn(boards[i]);
}

// fcb copy + qkv-bias concat + embedding, one launch
__global__ void misc_k(const float* __restrict__ fcb,
                       const float* __restrict__ sa_bq, const float* __restrict__ sa_bkv,
                       const int* __restrict__ moves,
                       const float* __restrict__ emb, const float* __restrict__ pos) {
    size_t i = (size_t)blockIdx.x * blockDim.x + threadIdx.x;
    if (i < VPAD) g_fcb[i] = (i < VOCAB) ? fcb[i] : 0.f;
    if (i < NLAY * 1536) {
        int l = (int)(i / 1536), j = (int)(i % 1536);
        g_bqkv[i] = (j < 512) ? sa_bq[l * 512 + j] : sa_bkv[l * 1024 + (j - 512)];
    }
    if (i < (size_t)NTOK * DD) {
        int tok = (int)(i / DD), d = (int)(i % DD);
        g_x[i] = emb[(size_t)moves[tok] * DD + d] * 22.62741699796952f
               + pos[(size_t)(tok % LL) * DD + d];
    }
}

// ---------------- layernorm v2: warp-per-row, 8 rows/block, float4 ----------------
__global__ __launch_bounds__(256) void ln_k(const float* __restrict__ X,
                                            const float* __restrict__ g,
                                            const float* __restrict__ b,
                                            __half* __restrict__ Y) {
    int row  = blockIdx.x * 8 + (threadIdx.x >> 5);
    int lane = threadIdx.x & 31;
    const float4* xp = (const float4*)(X + (size_t)row * DD) + lane * 4;
    float4 v0 = xp[0], v1 = xp[1], v2 = xp[2], v3 = xp[3];
    float s  = (v0.x + v0.y + v0.z + v0.w) + (v1.x + v1.y + v1.z + v1.w)
             + (v2.x + v2.y + v2.z + v2.w) + (v3.x + v3.y + v3.z + v3.w);
    float ss = (v0.x*v0.x + v0.y*v0.y + v0.z*v0.z + v0.w*v0.w)
             + (v1.x*v1.x + v1.y*v1.y + v1.z*v1.z + v1.w*v1.w)
             + (v2.x*v2.x + v2.y*v2.y + v2.z*v2.z + v2.w*v2.w)
             + (v3.x*v3.x + v3.y*v3.y + v3.z*v3.z + v3.w*v3.w);
    #pragma unroll
    for (int o = 16; o; o >>= 1) {
        s  += __shfl_xor_sync(0xffffffffu, s,  o);
        ss += __shfl_xor_sync(0xffffffffu, ss, o);
    }
    float mean = s * (1.0f / DD);
    float var  = ss * (1.0f / DD) - mean * mean;
    float rstd = rsqrtf(var + 1e-5f);
    const float4* gp = (const float4*)g + lane * 4;
    const float4* bp = (const float4*)b + lane * 4;
    float4 g0 = gp[0], g1 = gp[1], g2 = gp[2], g3 = gp[3];
    float4 b0 = bp[0], b1 = bp[1], b2 = bp[2], b3 = bp[3];
    __half2 o0[4], o1[4];
    o0[0] = __floats2half2_rn((v0.x-mean)*rstd*g0.x+b0.x, (v0.y-mean)*rstd*g0.y+b0.y);
    o0[1] = __floats2half2_rn((v0.z-mean)*rstd*g0.z+b0.z, (v0.w-mean)*rstd*g0.w+b0.w);
    o0[2] = __floats2half2_rn((v1.x-mean)*rstd*g1.x+b1.x, (v1.y-mean)*rstd*g1.y+b1.y);
    o0[3] = __floats2half2_rn((v1.z-mean)*rstd*g1.z+b1.z, (v1.w-mean)*rstd*g1.w+b1.w);
    o1[0] = __floats2half2_rn((v2.x-mean)*rstd*g2.x+b2.x, (v2.y-mean)*rstd*g2.y+b2.y);
    o1[1] = __floats2half2_rn((v2.z-mean)*rstd*g2.z+b2.z, (v2.w-mean)*rstd*g2.w+b2.w);
    o1[2] = __floats2half2_rn((v3.x-mean)*rstd*g3.x+b3.x, (v3.y-mean)*rstd*g3.y+b3.y);
    o1[3] = __floats2half2_rn((v3.z-mean)*rstd*g3.z+b3.z, (v3.w-mean)*rstd*g3.w+b3.w);
    uint4* yp = (uint4*)(Y + (size_t)row * DD + lane * 16);
    yp[0] = *(uint4*)o0;
    yp[1] = *(uint4*)o1;
}

#if TC5
__device__ __forceinline__ uint32_t elect1() {
    uint32_t p;
    asm volatile("{\n\t.reg .pred p;\n\telect.sync _|p, 0xFFFFFFFF;\n\tselp.b32 %0, 1, 0, p;\n\t}"
                 : "=r"(p));
    return p;
}
#endif

#define MB_WAIT(mbar, ph) do {                                                        \
    uint32_t _d;                                                                      \
    do {                                                                              \
        asm volatile("{\n\t.reg .pred p;\n\t"                                         \
            "mbarrier.try_wait.parity.acquire.cta.shared::cta.b64 p, [%1], %2, 0x989680;\n\t" \
            "selp.b32 %0, 1, 0, p;\n\t}"                                              \
            : "=r"(_d) : "r"(mbar), "r"((uint32_t)(ph)) : "memory");                  \
    } while (!_d);                                                                    \
} while (0)

// SW128 K-major descriptor base: layout=SW128(2), version=1, SBO=64, LBO=1
#define DESC_BASE ((2ull<<61)|(1ull<<46)|(64ull<<32)|(1ull<<16))
// idesc kind::f16: dtype=F32, atype=btype=F16(0), N=256, M=128
#define IDESC_F16 ((1u<<4) | (32u<<17) | (8u<<24))

#define STAGE_SZ 49152                 /* A 16KB + B 32KB */
#define TG_SMEM  (1024 + 2*STAGE_SZ)   /* 99328; 2 CTAs/SM */

// ---------------- GEMM: C[M,Nc] = A[M,K] @ Wt^T, 128x256 tiles, 2-stage ----------------
// epi: 0 +bias->f32  1 relu(+bias)->f16  2 +bias+res->f32  3 +bias->f16
__global__ __launch_bounds__(128, 2) void tgemm_k(
    const __half* __restrict__ A, const __half* __restrict__ Wt,
    const float* __restrict__ bias, const float* __restrict__ res,
    float* __restrict__ Cf, __half* __restrict__ Ch,
    int M, int N, int K, int Nc, int epi)
{
    extern __shared__ __align__(16) char smem[];
    const int tid  = threadIdx.x;
    const int lane = tid & 31;
    const int warp = tid >> 5;
    const int m0 = blockIdx.y * 128, n0 = blockIdx.x * 256;

#if TC5
    const uint32_t sb  = (uint32_t)__cvta_generic_to_shared(smem);
    const uint32_t MB0 = sb + 16;          // two mma-done barriers
    const uint32_t SMT = sb + 1024;
    const int KT = K >> 6;

    if (warp == 0) {
        asm volatile("tcgen05.alloc.cta_group::1.sync.aligned.shared::cta.b32 [%0], 256;"
                     :: "r"(sb) : "memory");
        asm volatile("tcgen05.relinquish_alloc_permit.cta_group::1.sync.aligned;");
    }
    if (tid == 0) {
        asm volatile("mbarrier.init.shared.b64 [%0], 1;" :: "r"(MB0)     : "memory");
        asm volatile("mbarrier.init.shared.b64 [%0], 1;" :: "r"(MB0 + 8) : "memory");
    }
    __syncthreads();
    uint32_t tmem;
    asm volatile("ld.shared.b32 %0, [%1];" : "=r"(tmem) : "r"(sb));

    const __half* Ab = A  + (size_t)m0 * K;
    const __half* Bb = Wt + (size_t)n0 * K;
    const uint32_t goB2 = (uint32_t)(K << 7);   // +128 rows (halves)

    uint32_t swo[8], go[8];
    #pragma unroll
    for (int i = 0; i < 8; i++) {
        int c = tid + i * 128;
        int row = c >> 3, cb = (c & 7) << 4;
        int bo = (row << 7) + cb;
        swo[i] = (uint32_t)(bo ^ ((bo >> 3) & 0x70));
        go[i]  = (uint32_t)(row * K + (cb >> 1));
    }

    #define LOADT(kt, s) do {                                                         \
        const __half* aP = Ab + (kt) * 64;                                            \
        const __half* bP = Bb + (kt) * 64;                                            \
        uint32_t baA = SMT + (s) * STAGE_SZ, baB = baA + 16384;                       \
        _Pragma("unroll")                                                             \
        for (int i = 0; i < 8; i++) {                                                 \
            asm volatile("cp.async.cg.shared.global [%0], [%1], 16;"                  \
                :: "r"(baA + swo[i]), "l"((const void*)(aP + go[i])) : "memory");     \
            asm volatile("cp.async.cg.shared.global [%0], [%1], 16;"                  \
                :: "r"(baB + swo[i]), "l"((const void*)(bP + go[i])) : "memory");     \
            asm volatile("cp.async.cg.shared.global [%0], [%1], 16;"                  \
                :: "r"(baB + 16384 + swo[i]), "l"((const void*)(bP + goB2 + go[i])) : "memory"); \
        }                                                                             \
        asm volatile("cp.async.commit_group;" ::: "memory");                          \
    } while (0)

    LOADT(0, 0);
    if (KT > 1) LOADT(1, 1);

    for (int kt = 0; kt < KT; kt++) {
        if (kt + 1 < KT) asm volatile("cp.async.wait_group 1;" ::: "memory");
        else             asm volatile("cp.async.wait_group 0;" ::: "memory");
        asm volatile("fence.proxy.async.shared::cta;" ::: "memory");
        __syncthreads();
        if (warp == 0 && elect1()) {
            uint32_t base = SMT + (kt & 1) * STAGE_SZ;
            uint64_t ad = DESC_BASE | (uint64_t)((base >> 4) & 0x3FFF);
            uint64_t bd = DESC_BASE | (uint64_t)(((base + 16384) >> 4) & 0x3FFF);
            #pragma unroll
            for (int s = 0; s < 4; s++) {
                uint32_t en = (kt > 0 || s > 0) ? 1u : 0u;
                asm volatile(
                    "{\n\t.reg .pred p;\n\tsetp.ne.u32 p, %5, 0;\n\t"
                    "tcgen05.mma.cta_group::1.kind::f16 [%0], %1, %2, %3, {%4,%4,%4,%4}, p;\n\t}"
                    :: "r"(tmem), "l"(ad + s * 2), "l"(bd + s * 2),
                       "r"(IDESC_F16), "r"(0u), "r"(en) : "memory");
            }
            asm volatile(
                "tcgen05.commit.cta_group::1.mbarrier::arrive::one.shared::cluster.b64 [%0];"
                :: "r"(MB0 + (uint32_t)(kt & 1) * 8) : "memory");
        }
        if (kt + 2 < KT) {
            MB_WAIT(MB0 + (uint32_t)(kt & 1) * 8, (uint32_t)((kt >> 1) & 1));
            LOADT(kt + 2, kt & 1);
        }
    }
    {
        int j = KT - 1;
        MB_WAIT(MB0 + (uint32_t)(j & 1) * 8, (uint32_t)((j >> 1) & 1));
    }
    asm volatile("tcgen05.fence::after_thread_sync;" ::: "memory");
    __syncthreads();

    // ---- epilogue: 64-col chunks staged in smem, vectorized coalesced stores ----
    float* osm = (float*)(smem + 1024);          // [128][66]
    for (int cb = 0; cb < 256; cb += 64) {
        uint32_t d0[32], d1[32];
        asm volatile(
            "tcgen05.ld.sync.aligned.32x32b.x32.b32 "
            "{%0,%1,%2,%3,%4,%5,%6,%7,%8,%9,%10,%11,%12,%13,%14,%15,"
            "%16,%17,%18,%19,%20,%21,%22,%23,%24,%25,%26,%27,%28,%29,%30,%31}, [%32];"
            : "=r"(d0[0]),"=r"(d0[1]),"=r"(d0[2]),"=r"(d0[3]),"=r"(d0[4]),"=r"(d0[5]),
              "=r"(d0[6]),"=r"(d0[7]),"=r"(d0[8]),"=r"(d0[9]),"=r"(d0[10]),"=r"(d0[11]),
              "=r"(d0[12]),"=r"(d0[13]),"=r"(d0[14]),"=r"(d0[15]),"=r"(d0[16]),"=r"(d0[17]),
              "=r"(d0[18]),"=r"(d0[19]),"=r"(d0[20]),"=r"(d0[21]),"=r"(d0[22]),"=r"(d0[23]),
              "=r"(d0[24]),"=r"(d0[25]),"=r"(d0[26]),"=r"(d0[27]),"=r"(d0[28]),"=r"(d0[29]),
              "=r"(d0[30]),"=r"(d0[31])
            : "r"(tmem + cb));
        asm volatile(
            "tcgen05.ld.sync.aligned.32x32b.x32.b32 "
            "{%0,%1,%2,%3,%4,%5,%6,%7,%8,%9,%10,%11,%12,%13,%14,%15,"
            "%16,%17,%18,%19,%20,%21,%22,%23,%24,%25,%26,%27,%28,%29,%30,%31}, [%32];"
            : "=r"(d1[0]),"=r"(d1[1]),"=r"(d1[2]),"=r"(d1[3]),"=r"(d1[4]),"=r"(d1[5]),
              "=r"(d1[6]),"=r"(d1[7]),"=r"(d1[8]),"=r"(d1[9]),"=r"(d1[10]),"=r"(d1[11]),
              "=r"(d1[12]),"=r"(d1[13]),"=r"(d1[14]),"=r"(d1[15]),"=r"(d1[16]),"=r"(d1[17]),
              "=r"(d1[18]),"=r"(d1[19]),"=r"(d1[20]),"=r"(d1[21]),"=r"(d1[22]),"=r"(d1[23]),
              "=r"(d1[24]),"=r"(d1[25]),"=r"(d1[26]),"=r"(d1[27]),"=r"(d1[28]),"=r"(d1[29]),
              "=r"(d1[30]),"=r"(d1[31])
            : "r"(tmem + cb + 32));
        asm volatile("tcgen05.wait::ld.sync.aligned;" ::: "memory");
        float* rowp = osm + tid * 66;
        #pragma unroll
        for (int c = 0; c < 32; c++) { rowp[c] = __uint_as_float(d0[c]); rowp[32 + c] = __uint_as_float(d1[c]); }
        __syncthreads();
        const int colb = n0 + cb;
        const int c2 = lane * 2;
        if (colb + 64 <= Nc) {
            float b0 = bias[colb + c2], b1 = bias[colb + c2 + 1];
            for (int rr = warp; rr < 128; rr += 4) {
                float v0 = osm[rr * 66 + c2] + b0;
                float v1 = osm[rr * 66 + c2 + 1] + b1;
                size_t off = (size_t)(m0 + rr) * Nc + colb + c2;
                if (epi == 2) {
                    float2 rv = *(const float2*)(res + off);
                    *(float2*)(Cf + off) = make_float2(v0 + rv.x, v1 + rv.y);
                } else if (epi == 0) {
                    *(float2*)(Cf + off) = make_float2(v0, v1);
                } else {
                    if (epi == 1) { v0 = fmaxf(v0, 0.f); v1 = fmaxf(v1, 0.f); }
                    *(__half2*)(Ch + off) = __floats2half2_rn(v0, v1);
                }
            }
        } else {
            for (int rr = warp; rr < 128; rr += 4) {
                #pragma unroll
                for (int q = 0; q < 2; q++) {
                    int c = colb + c2 + q;
                    if (c < Nc) {
                        float v = osm[rr * 66 + c2 + q] + bias[c];
                        size_t off = (size_t)(m0 + rr) * Nc + c;
                        if (epi == 2)      Cf[off] = v + res[off];
                        else if (epi == 0) Cf[off] = v;
                        else if (epi == 1) Ch[off] = __float2half_rn(fmaxf(v, 0.f));
                        else               Ch[off] = __float2half_rn(v);
                    }
                }
            }
        }
        __syncthreads();
    }

    if (tid == 0) {
        asm volatile("mbarrier.inval.shared.b64 [%0];" :: "r"(MB0)     : "memory");
        asm volatile("mbarrier.inval.shared.b64 [%0];" :: "r"(MB0 + 8) : "memory");
    }
    __syncthreads();
    if (warp == 0)
        asm volatile("tcgen05.dealloc.cta_group::1.sync.aligned.b32 %0, 256;" :: "r"(tmem));
    #undef LOADT

#else
    // ===== naive fallback (never executed on sm_103a; kept for non-'a' pass validity) =====
    for (int idx = tid; idx < 128 * 256; idx += 128) {
        int m = m0 + idx / 256;
        int n = n0 + (idx % 256);
        if (m < M && n < Nc) {
            float acc = bias[n];
            const __half* ap = A + (size_t)m * K;
            const __half* wp = Wt + (size_t)n * K;
            for (int k = 0; k < K; k++) acc += __half2float(ap[k]) * __half2float(wp[k]);
            size_t off = (size_t)m * Nc + n;
            if (epi == 0)      Cf[off] = acc;
            else if (epi == 1) Ch[off] = __float2half_rn(fmaxf(acc, 0.f));
            else if (epi == 2) Cf[off] = acc + res[off];
            else               Ch[off] = __float2half_rn(acc);
        }
    }
#endif
}

// ---------------- self attention v2: per (b,h), half2 smem, 128 threads ----------------
__global__ __launch_bounds__(128) void selfattn_k(const __half* __restrict__ QKV,
                                                  const int* __restrict__ lengths,
                                                  __half* __restrict__ O) {
    int b = blockIdx.x, h = blockIdx.y;
    __shared__ __half2 qs[LL][33], ks[LL][33], vs[LL][33];
    __shared__ float s[LL][12];
    int tid = threadIdx.x;
    int len = lengths[b];
    const __half2* base = (const __half2*)QKV + ((size_t)b * LL) * 768 + h * 32;
    for (int idx = tid; idx < LL * 32; idx += 128) {
        int i = idx >> 5, d2 = idx & 31;
        const __half2* rp = base + (size_t)i * 768 + d2;
        qs[i][d2] = rp[0];
        ks[i][d2] = rp[256];
        vs[i][d2] = rp[512];
    }
    __syncthreads();
    for (int idx = tid; idx < LL * LL; idx += 128) {
        int i = idx / LL, j = idx % LL;
        float acc = 0.f;
        if (j <= i && j < len) {
            #pragma unroll
            for (int d2 = 0; d2 < 32; d2++) {
                float2 qv = __half22float2(qs[i][d2]);
                float2 kv = __half22float2(ks[j][d2]);
                acc += qv.x * kv.x + qv.y * kv.y;
            }
            acc *= 0.125f;
        } else acc = -1e30f;
        s[i][j] = acc;
    }
    __syncthreads();
    if (tid < LL) {
        float mx = -1e30f;
        #pragma unroll
        for (int j = 0; j < LL; j++) mx = fmaxf(mx, s[tid][j]);
        float sum = 0.f;
        #pragma unroll
        for (int j = 0; j < LL; j++) { float e = expf(s[tid][j] - mx); s[tid][j] = e; sum += e; }
        float inv = 1.0f / sum;
        #pragma unroll
        for (int j = 0; j < LL; j++) s[tid][j] *= inv;
    }
    __syncthreads();
    __half2* ob = (__half2*)O + ((size_t)b * LL) * 256 + h * 32;
    for (int idx = tid; idx < LL * 32; idx += 128) {
        int i = idx >> 5, d2 = idx & 31;
        float ax = 0.f, ay = 0.f;
        #pragma unroll
        for (int j = 0; j < LL; j++) {
            float sv = s[i][j];
            float2 vv = __half22float2(vs[j][d2]);
            ax += sv * vv.x; ay += sv * vv.y;
        }
        ob[(size_t)i * 256 + d2] = __floats2half2_rn(ax, ay);
    }
}

// ---------------- cross attention v2: per (b,h), half2 smem, 256 threads ----------------
__global__ __launch_bounds__(256) void crossattn_k(const __half* __restrict__ Q,
                                                   const __half* __restrict__ CKV,
                                                   __half* __restrict__ O) {
    int b = blockIdx.x, h = blockIdx.y;
    __shared__ __half2 qs[LL][33];
    __shared__ __half2 ks[BOARD][33], vs[BOARD][33];
    __shared__ float s[LL][72];
    int tid = threadIdx.x;

    const __half2* qb = (const __half2*)Q + ((size_t)b * LL) * 256 + h * 32;
    for (int idx = tid; idx < LL * 32; idx += 256) {
        int i = idx >> 5, d2 = idx & 31;
        qs[i][d2] = qb[(size_t)i * 256 + d2];
    }
    const __half2* cb = (const __half2*)CKV + ((size_t)b * BOARD) * 512 + h * 32;
    for (int idx = tid; idx < BOARD * 32; idx += 256) {
        int j = idx >> 5, d2 = idx & 31;
        const __half2* rp = cb + (size_t)j * 512 + d2;
        ks[j][d2] = rp[0];
        vs[j][d2] = rp[256];
    }
    __syncthreads();

    // scores: thread handles (i, 4 consecutive j)
    {
        int idx = tid;                 // 10 * 18 = 180 work items
        if (idx < 180) {
            int i = idx / 18, g = idx % 18;
            int j0 = g * 4;
            float a0 = 0.f, a1 = 0.f, a2 = 0.f, a3 = 0.f;
            #pragma unroll
            for (int d2 = 0; d2 < 32; d2++) {
                float2 qv = __half22float2(qs[i][d2]);
                float2 k0 = __half22float2(ks[j0][d2]);
                a0 += qv.x * k0.x + qv.y * k0.y;
                if (j0 + 1 < BOARD) { float2 k1 = __half22float2(ks[j0+1][d2]); a1 += qv.x * k1.x + qv.y * k1.y; }
                if (j0 + 2 < BOARD) { float2 k2 = __half22float2(ks[j0+2][d2]); a2 += qv.x * k2.x + qv.y * k2.y; }
                if (j0 + 3 < BOARD) { float2 k3 = __half22float2(ks[j0+3][d2]); a3 += qv.x * k3.x + qv.y * k3.y; }
            }
            s[i][j0] = a0 * 0.125f;
            if (j0 + 1 < BOARD) s[i][j0+1] = a1 * 0.125f;
            if (j0 + 2 < BOARD) s[i][j0+2] = a2 * 0.125f;
            if (j0 + 3 < BOARD) s[i][j0+3] = a3 * 0.125f;
        }
    }
    __syncthreads();

    // softmax: warp w handles row w (w<8); rows 8,9 by warps 0,1 (second pass)
    {
        int warp = tid >> 5, lane = tid & 31;
        for (int pass = 0; pass < 2; pass++) {
            int row = warp + pass * 8;
            if (row < LL && (pass == 0 || warp < 2)) {
                float m0 = -1e30f;
                float v0 = (lane < BOARD)      ? s[row][lane]      : -1e30f;
                float v1 = (lane + 32 < BOARD) ? s[row][lane + 32] : -1e30f;
                float v2 = (lane + 64 < BOARD) ? s[row][lane + 64] : -1e30f;
                m0 = fmaxf(fmaxf(v0, v1), v2);
                #pragma unroll
                for (int o = 16; o; o >>= 1) m0 = fmaxf(m0, __shfl_xor_sync(0xffffffffu, m0, o));
                float e0 = (lane < BOARD)      ? expf(v0 - m0) : 0.f;
                float e1 = (lane + 32 < BOARD) ? expf(v1 - m0) : 0.f;
                float e2 = (lane + 64 < BOARD) ? expf(v2 - m0) : 0.f;
                float sm = e0 + e1 + e2;
                #pragma unroll
                for (int o = 16; o; o >>= 1) sm += __shfl_xor_sync(0xffffffffu, sm, o);
                float inv = 1.0f / sm;
                if (lane < BOARD)      s[row][lane]      = e0 * inv;
                if (lane + 32 < BOARD) s[row][lane + 32] = e1 * inv;
                if (lane + 64 < BOARD) s[row][lane + 64] = e2 * inv;
            }
        }
    }
    __syncthreads();

    // AV: thread handles (i2, d2) computing rows i2 and i2+5; V read once per pair
    {
        int idx = tid;                 // 5 * 32 = 160 work items
        if (idx < 160) {
            int i2 = idx >> 5, d2 = idx & 31;
            float ax0 = 0.f, ay0 = 0.f, ax1 = 0.f, ay1 = 0.f;
            #pragma unroll 2
            for (int j = 0; j < BOARD; j++) {
                float2 vv = __half22float2(vs[j][d2]);
                float s0 = s[i2][j], s1 = s[i2 + 5][j];
                ax0 += s0 * vv.x; ay0 += s0 * vv.y;
                ax1 += s1 * vv.x; ay1 += s1 * vv.y;
            }
            __half2* ob = (__half2*)O + ((size_t)b * LL) * 256 + h * 32 + d2;
            ob[(size_t)i2 * 256]       = __floats2half2_rn(ax0, ay0);
            ob[(size_t)(i2 + 5) * 256] = __floats2half2_rn(ax1, ay1);
        }
    }
}

// ---------------- host ----------------
static __half* s_wt;

static void tgemm_s(cudaStream_t st, const __half* A, size_t woff, const float* bias,
                    const float* res, float* Cf, __half* Ch,
                    int M, int N, int K, int Nc, int epi) {
    dim3 grid(N / 256, M / 128);
    tgemm_k<<<grid, 128, TG_SMEM, st>>>(A, s_wt + woff, bias, res, Cf, Ch, M, N, K, Nc, epi);
}

extern "C" void kernel_launch(void* const* d_in, const int* in_sizes, int n_in,
                              void* d_out, int out_size) {
    const int*   moves   = (const int*)d_in[0];
    const int*   lengths = (const int*)d_in[1];
    const float* boards  = (const float*)d_in[2];
    const float* emb     = (const float*)d_in[3];
    const float* pos     = (const float*)d_in[4];
    const float* sa_ln_g = (const float*)d_in[5];
    const float* sa_ln_b = (const float*)d_in[6];
    const float* sa_wq   = (const float*)d_in[7];
    const float* sa_bq   = (const float*)d_in[8];
    const float* sa_wkv  = (const float*)d_in[9];
    const float* sa_bkv  = (const float*)d_in[10];
    const float* sa_wo   = (const float*)d_in[11];
    const float* sa_bo   = (const float*)d_in[12];
    const float* ca_ln_g = (const float*)d_in[13];
    const float* ca_ln_b = (const float*)d_in[14];
    const float* ca_wq   = (const float*)d_in[15];
    const float* ca_bq   = (const float*)d_in[16];
    const float* ca_wkv  = (const float*)d_in[17];
    const float* ca_bkv  = (const float*)d_in[18];
    const float* ca_wo   = (const float*)d_in[19];
    const float* ca_bo   = (const float*)d_in[20];
    const float* ff_ln_g = (const float*)d_in[21];
    const float* ff_ln_b = (const float*)d_in[22];
    const float* ff_w1   = (const float*)d_in[23];
    const float* ff_b1   = (const float*)d_in[24];
    const float* ff_w2   = (const float*)d_in[25];
    const float* ff_b2   = (const float*)d_in[26];
    const float* fin_g   = (const float*)d_in[27];
    const float* fin_b   = (const float*)d_in[28];
    const float* fc_w    = (const float*)d_in[29];
    const float* fc_b    = (const float*)d_in[30];
    float* out = (float*)d_out;

    // one-time infra (created on the uncaptured correctness call)
    static cudaStream_t s2 = nullptr;
    static cudaEvent_t evB = nullptr;
    static cudaEvent_t evK[NLAY];
    if (!s2) {
        cudaStreamCreateWithFlags(&s2, cudaStreamNonBlocking);
        cudaEventCreateWithFlags(&evB, cudaEventDisableTiming);
        for (int i = 0; i < NLAY; i++)
            cudaEventCreateWithFlags(&evK[i], cudaEventDisableTiming);
        cudaFuncSetAttribute(tgemm_k, cudaFuncAttributeMaxDynamicSharedMemorySize, TG_SMEM);
    }

    float *px, *pfcb, *pbqkv;
    __half *pxn, *pq, *pqkv, *pao, *ph, *pckv, *pbf;
    cudaGetSymbolAddress((void**)&px,    g_x);
    cudaGetSymbolAddress((void**)&pfcb,  g_fcb);
    cudaGetSymbolAddress((void**)&pbqkv, g_bqkv);
    cudaGetSymbolAddress((void**)&pxn,   g_xn);
    cudaGetSymbolAddress((void**)&pq,    g_q);
    cudaGetSymbolAddress((void**)&pqkv,  g_qkv);
    cudaGetSymbolAddress((void**)&pao,   g_ao);
    cudaGetSymbolAddress((void**)&ph,    g_h);
    cudaGetSymbolAddress((void**)&pckv,  g_ckv);
    cudaGetSymbolAddress((void**)&pbf,   g_bf);
    cudaGetSymbolAddress((void**)&s_wt,  g_wt);

    // prep on main stream
    wprep_k<<<(unsigned)((WTOT + 511) / 512), 512>>>(sa_wq, sa_wkv, sa_wo, ca_wq, ca_wkv,
                                                     ca_wo, ff_w1, ff_w2, fc_w);
    bconv_k<<<(unsigned)(((size_t)NBRD * DD) / 512), 512>>>(boards);
    cudaEventRecord(evB, 0);
    misc_k<<<(NTOK * DD) / 512, 512>>>(fc_b, sa_bq, sa_bkv, moves, emb, pos);

    // side stream: all six cross-KV GEMMs (depend only on boards + weights)
    cudaStreamWaitEvent(s2, evB, 0);
    for (int i = 0; i < NLAY; i++) {
        tgemm_s(s2, pbf, (size_t)i * PL + R_CAKV, ca_bkv + i * 1024, nullptr,
                nullptr, pckv + (size_t)i * CKVSZ, NBRD, 1024, 512, 1024, 3);
        cudaEventRecord(evK[i], s2);
    }

    for (int i = 0; i < NLAY; i++) {
        size_t WB = (size_t)i * PL;

        // ---- self attention ----
        ln_k<<<NTOK / 8, 256>>>(px, sa_ln_g + i * DD, sa_ln_b + i * DD, pxn);
        tgemm_s(0, pxn, WB + R_SAQKV, pbqkv + i * 1536, nullptr, nullptr, pqkv,
                NTOK, 1536, 512, 1536, 3);
        selfattn_k<<<dim3(BB, HH), 128>>>(pqkv, lengths, pao);
        tgemm_s(0, pao, WB + R_SAO, sa_bo + i * DD, px, px, nullptr,
                NTOK, 512, 512, 512, 2);

        // ---- cross attention ----
        ln_k<<<NTOK / 8, 256>>>(px, ca_ln_g + i * DD, ca_ln_b + i * DD, pxn);
        tgemm_s(0, pxn, WB + R_CAQ, ca_bq + i * 512, nullptr, nullptr, pq,
                NTOK, 512, 512, 512, 3);
        cudaStreamWaitEvent(0, evK[i], 0);
        crossattn_k<<<dim3(BB, HH), 256>>>(pq, pckv + (size_t)i * CKVSZ, pao);
        tgemm_s(0, pao, WB + R_CAO, ca_bo + i * DD, px, px, nullptr,
                NTOK, 512, 512, 512, 2);

        // ---- FFN ----
        ln_k<<<NTOK / 8, 256>>>(px, ff_ln_g + i * DD, ff_ln_b + i * DD, pxn);
        tgemm_s(0, pxn, WB + R_FF1, ff_b1 + i * DI, nullptr, nullptr, ph,
                NTOK, DI, 512, DI, 1);
        tgemm_s(0, ph, WB + R_FF2, ff_b2 + i * DD, px, px, nullptr,
                NTOK, 512, DI, 512, 2);
    }

    ln_k<<<NTOK / 8, 256>>>(px, fin_g, fin_b, pxn);
    tgemm_s(0, pxn, OFF_FC, pfcb, nullptr, out, nullptr, NTOK, VPAD, 512, VOCAB, 0);
}